// round 1
// baseline (speedup 1.0000x reference)
#include <cuda_runtime.h>
#include <math.h>

#define FULLMASK 0xffffffffu

// Problem constants
#define B_    8
#define NQ_   900
#define C_    256
#define M_    8
#define L_    4
#define P_    4
#define D_    32
#define S_    19560
#define FFN_  1024
#define NC_   10
#define R_    (B_*NQ_)          // 7200 rows (b,q)
#define RT_   ((R_ + 63) / 64)  // 113 row tiles

// ---------------- scratch (static device globals; no allocation) ----------------
__device__ float g_off  [R_ * C_];          // query @ w_off + b_off        [7200,256]
__device__ float g_attn [R_ * M_ * 16];     // raw attn logits              [7200,128]
__device__ float g_agg  [R_ * M_ * C_];     // aggregated value rows        [7200,8,256]
__device__ float g_wsum [R_ * M_];          // summed valid weights         [7200,8]
__device__ float g_featv[R_ * C_];          // per-head projected features  [7200,256]
__device__ float g_feat [R_ * C_];          // after w_out                  [7200,256]
__device__ float g_x1   [R_ * C_];          // after LN1                    [7200,256]
__device__ float g_h    [R_ * FFN_];        // FFN hidden                   [7200,1024]
__device__ float g_h2   [R_ * C_];          // after w_ffn2                 [7200,256]

// ---------------- generic fp32 tiled GEMM: C = A[M,K] @ W[K,N] + bias ----------------
// BM=64, BN=64, BK=16, 256 threads, 4x4 microtile.
template<bool RELU>
__global__ __launch_bounds__(256) void gemm64_kernel(
    const float* __restrict__ A, int lda,
    const float* __restrict__ W, int ldw,
    const float* __restrict__ bias,
    float* __restrict__ Cout, int ldc,
    int Mrows, int K)
{
    __shared__ float As[16][68];   // transposed: As[k][m], row stride 272B = 17*16B (f4-aligned)
    __shared__ float Ws[16][64];

    const int tid = threadIdx.x;
    const int tx  = tid & 15, ty = tid >> 4;
    const int row0 = blockIdx.x * 64, col0 = blockIdx.y * 64;

    const int arow = tid >> 2;            // 0..63
    const int akq  = (tid & 3) << 2;      // 0,4,8,12
    const int wrow = tid >> 4;            // 0..15
    const int wnq  = (tid & 15) << 2;     // 0..60

    const bool avalid = (row0 + arow) < Mrows;
    const float* Ap = A + (size_t)(row0 + arow) * lda + akq;
    const float* Wp = W + (size_t)wrow * ldw + col0 + wnq;

    float acc[4][4];
    #pragma unroll
    for (int i = 0; i < 4; i++)
        #pragma unroll
        for (int j = 0; j < 4; j++) acc[i][j] = 0.f;

    for (int k0 = 0; k0 < K; k0 += 16) {
        float4 av = avalid ? *(const float4*)(Ap + k0) : make_float4(0.f, 0.f, 0.f, 0.f);
        float4 wv = *(const float4*)(Wp + (size_t)k0 * ldw);
        As[akq + 0][arow] = av.x;
        As[akq + 1][arow] = av.y;
        As[akq + 2][arow] = av.z;
        As[akq + 3][arow] = av.w;
        *(float4*)&Ws[wrow][wnq] = wv;
        __syncthreads();
        #pragma unroll
        for (int kk = 0; kk < 16; kk++) {
            float4 a4 = *(const float4*)&As[kk][ty << 2];
            float4 w4 = *(const float4*)&Ws[kk][tx << 2];
            float ar[4] = {a4.x, a4.y, a4.z, a4.w};
            float wr[4] = {w4.x, w4.y, w4.z, w4.w};
            #pragma unroll
            for (int i = 0; i < 4; i++)
                #pragma unroll
                for (int j = 0; j < 4; j++)
                    acc[i][j] = fmaf(ar[i], wr[j], acc[i][j]);
        }
        __syncthreads();
    }

    float bv[4];
    #pragma unroll
    for (int j = 0; j < 4; j++) bv[j] = bias[col0 + (tx << 2) + j];

    #pragma unroll
    for (int i = 0; i < 4; i++) {
        int row = row0 + (ty << 2) + i;
        if (row < Mrows) {
            float v0 = acc[i][0] + bv[0];
            float v1 = acc[i][1] + bv[1];
            float v2 = acc[i][2] + bv[2];
            float v3 = acc[i][3] + bv[3];
            if (RELU) {
                v0 = fmaxf(v0, 0.f); v1 = fmaxf(v1, 0.f);
                v2 = fmaxf(v2, 0.f); v3 = fmaxf(v3, 0.f);
            }
            float4 o; o.x = v0; o.y = v1; o.z = v2; o.w = v3;
            *(float4*)&Cout[(size_t)row * ldc + col0 + (tx << 2)] = o;
        }
    }
}

// ---------------- per-head projection: featv[r, m*32+n] = agg[r,m,:] . Wv[:, m*32+n] + wsum*bv ----------------
// BM=64, BN=32, BK=16, 256 threads, 4x2 microtile. grid = (113, 1, 8 heads)
__global__ __launch_bounds__(256) void head_gemm_kernel(
    const float* __restrict__ w_value, const float* __restrict__ b_value)
{
    const int m = blockIdx.z;
    __shared__ float As[16][68];
    __shared__ float Ws[16][32];

    const int tid = threadIdx.x;
    const int tx  = tid & 15, ty = tid >> 4;
    const int row0 = blockIdx.x * 64;

    const int arow = tid >> 2;
    const int akq  = (tid & 3) << 2;
    const int wrow = tid >> 4;
    const int wnq  = (tid & 15) << 1;     // 0..30 step 2

    const bool avalid = (row0 + arow) < R_;
    const float* Ap = g_agg + ((size_t)(row0 + arow) * M_ + m) * C_ + akq;
    const float* Wp = w_value + (size_t)wrow * C_ + m * D_ + wnq;

    float acc[4][2];
    #pragma unroll
    for (int i = 0; i < 4; i++) { acc[i][0] = 0.f; acc[i][1] = 0.f; }

    for (int k0 = 0; k0 < C_; k0 += 16) {
        float4 av = avalid ? *(const float4*)(Ap + k0) : make_float4(0.f, 0.f, 0.f, 0.f);
        float2 wv = *(const float2*)(Wp + (size_t)k0 * C_);
        As[akq + 0][arow] = av.x;
        As[akq + 1][arow] = av.y;
        As[akq + 2][arow] = av.z;
        As[akq + 3][arow] = av.w;
        *(float2*)&Ws[wrow][wnq] = wv;
        __syncthreads();
        #pragma unroll
        for (int kk = 0; kk < 16; kk++) {
            float4 a4 = *(const float4*)&As[kk][ty << 2];
            float2 w2 = *(const float2*)&Ws[kk][tx << 1];
            float ar[4] = {a4.x, a4.y, a4.z, a4.w};
            #pragma unroll
            for (int i = 0; i < 4; i++) {
                acc[i][0] = fmaf(ar[i], w2.x, acc[i][0]);
                acc[i][1] = fmaf(ar[i], w2.y, acc[i][1]);
            }
        }
        __syncthreads();
    }

    const float b0 = b_value[m * D_ + (tx << 1) + 0];
    const float b1 = b_value[m * D_ + (tx << 1) + 1];
    #pragma unroll
    for (int i = 0; i < 4; i++) {
        int row = row0 + (ty << 2) + i;
        if (row < R_) {
            float ws = g_wsum[(size_t)row * M_ + m];
            float2 o;
            o.x = acc[i][0] + ws * b0;
            o.y = acc[i][1] + ws * b1;
            *(float2*)&g_featv[(size_t)row * C_ + m * D_ + (tx << 1)] = o;
        }
    }
}

// ---------------- deformable sampling + aggregation ----------------
// block = one (b,q); warp m handles head m. Inline softmax over the 16 (l,p) logits.
// Aggregates raw value rows (full C=256) with combined attn*bilinear*valid weights.
__global__ __launch_bounds__(256) void sample_agg_kernel(
    const float* __restrict__ value, const float* __restrict__ ref_points)
{
    const int r    = blockIdx.x;           // b*NQ + q
    const int b    = r / NQ_;
    const int m    = threadIdx.x >> 5;
    const int lane = threadIdx.x & 31;

    const float rx = ref_points[r * 2 + 0];
    const float ry = ref_points[r * 2 + 1];

    // softmax over 16 attn logits (lanes 0..15 hold them)
    float araw = (lane < 16) ? g_attn[(size_t)r * 128 + m * 16 + lane] : -1e30f;
    float amax = araw;
    #pragma unroll
    for (int o = 8; o; o >>= 1) amax = fmaxf(amax, __shfl_xor_sync(FULLMASK, amax, o, 16));
    float e = (lane < 16) ? __expf(araw - amax) : 0.f;
    float es = e;
    #pragma unroll
    for (int o = 8; o; o >>= 1) es += __shfl_xor_sync(FULLMASK, es, o, 16);
    const float anorm = e / es;   // valid on lanes 0..15 (only those are shfl'd)

    // offsets: lane holds off[m, lane] of the 32 per-head offset scalars
    const float offv = g_off[(size_t)r * C_ + m * 32 + lane];

    float a0[4] = {0.f, 0.f, 0.f, 0.f};
    float a1[4] = {0.f, 0.f, 0.f, 0.f};
    float wsum = 0.f;

    const int Hs[4]  = {92, 46, 23, 12};
    const int Wls[4] = {160, 80, 40, 20};
    const int St[4]  = {0, 14720, 18400, 19320};
    const float* vb = value + (size_t)b * S_ * C_;

#define ACCUM(ptr, wgt) do {                                          \
        const float4* _p4 = (const float4*)(ptr);                     \
        float4 _v0 = _p4[lane];                                       \
        float4 _v1 = _p4[32 + lane];                                  \
        a0[0] = fmaf(wgt, _v0.x, a0[0]);                              \
        a0[1] = fmaf(wgt, _v0.y, a0[1]);                              \
        a0[2] = fmaf(wgt, _v0.z, a0[2]);                              \
        a0[3] = fmaf(wgt, _v0.w, a0[3]);                              \
        a1[0] = fmaf(wgt, _v1.x, a1[0]);                              \
        a1[1] = fmaf(wgt, _v1.y, a1[1]);                              \
        a1[2] = fmaf(wgt, _v1.z, a1[2]);                              \
        a1[3] = fmaf(wgt, _v1.w, a1[3]);                              \
    } while (0)

    #pragma unroll
    for (int l = 0; l < 4; l++) {
        const int Hl = Hs[l], Wl = Wls[l];
        const float invW = 1.f / (float)Wl, invH = 1.f / (float)Hl;
        const float* lb = vb + (size_t)St[l] * C_;
        #pragma unroll
        for (int p = 0; p < 4; p++) {
            const int pt = l * 4 + p;
            const float a  = __shfl_sync(FULLMASK, anorm, pt);
            const float ox = __shfl_sync(FULLMASK, offv, 2 * pt);
            const float oy = __shfl_sync(FULLMASK, offv, 2 * pt + 1);
            // mirror reference: loc = ref + off/norm ; x = loc*W - 0.5
            const float x = (rx + ox * invW) * (float)Wl - 0.5f;
            const float y = (ry + oy * invH) * (float)Hl - 0.5f;
            const float xf = floorf(x), yf = floorf(y);
            const int   x0 = (int)xf,   y0 = (int)yf;
            const float lx = x - xf,    ly = y - yf;
            const float w00 = a * (1.f - lx) * (1.f - ly);
            const float w01 = a * lx * (1.f - ly);
            const float w10 = a * (1.f - lx) * ly;
            const float w11 = a * lx * ly;
            const bool vx0 = (unsigned)x0       < (unsigned)Wl;
            const bool vx1 = (unsigned)(x0 + 1) < (unsigned)Wl;
            const bool vy0 = (unsigned)y0       < (unsigned)Hl;
            const bool vy1 = (unsigned)(y0 + 1) < (unsigned)Hl;
            if (vy0) {
                const float* rp = lb + (size_t)y0 * Wl * C_;
                if (vx0) { ACCUM(rp + (size_t)x0 * C_,       w00); wsum += w00; }
                if (vx1) { ACCUM(rp + (size_t)(x0 + 1) * C_, w01); wsum += w01; }
            }
            if (vy1) {
                const float* rp = lb + (size_t)(y0 + 1) * Wl * C_;
                if (vx0) { ACCUM(rp + (size_t)x0 * C_,       w10); wsum += w10; }
                if (vx1) { ACCUM(rp + (size_t)(x0 + 1) * C_, w11); wsum += w11; }
            }
        }
    }
#undef ACCUM

    float* ag = g_agg + ((size_t)r * M_ + m) * C_;
    *(float4*)&ag[lane * 4]       = make_float4(a0[0], a0[1], a0[2], a0[3]);
    *(float4*)&ag[128 + lane * 4] = make_float4(a1[0], a1[1], a1[2], a1[3]);
    if (lane == 0) g_wsum[(size_t)r * M_ + m] = wsum;
}

// ---------------- LayerNorm helpers ----------------
__global__ __launch_bounds__(256) void ln1_kernel(
    const float* __restrict__ query,
    const float* __restrict__ lw, const float* __restrict__ lb)
{
    const int r = blockIdx.x, t = threadIdx.x;
    const size_t idx = (size_t)r * C_ + t;
    float v = query[idx] + g_feat[idx];

    __shared__ float s1[8], s2[8];
    float sum = v, sq = v * v;
    #pragma unroll
    for (int o = 16; o; o >>= 1) {
        sum += __shfl_xor_sync(FULLMASK, sum, o);
        sq  += __shfl_xor_sync(FULLMASK, sq, o);
    }
    const int lane = t & 31, wp = t >> 5;
    if (lane == 0) { s1[wp] = sum; s2[wp] = sq; }
    __syncthreads();
    float tot = 0.f, totq = 0.f;
    #pragma unroll
    for (int i = 0; i < 8; i++) { tot += s1[i]; totq += s2[i]; }
    const float mu  = tot * (1.f / 256.f);
    const float var = totq * (1.f / 256.f) - mu * mu;
    const float rs  = rsqrtf(var + 1e-6f);
    g_x1[idx] = (v - mu) * rs * lw[t] + lb[t];
}

__global__ __launch_bounds__(256) void ln2_cls_kernel(
    const float* __restrict__ lw, const float* __restrict__ lb,
    const float* __restrict__ wcls, const float* __restrict__ bcls,
    float* __restrict__ out)
{
    const int r = blockIdx.x, t = threadIdx.x;
    const size_t idx = (size_t)r * C_ + t;
    float v = g_x1[idx] + g_h2[idx];

    __shared__ float s1[8], s2[8];
    __shared__ float sred[8][10];
    float sum = v, sq = v * v;
    #pragma unroll
    for (int o = 16; o; o >>= 1) {
        sum += __shfl_xor_sync(FULLMASK, sum, o);
        sq  += __shfl_xor_sync(FULLMASK, sq, o);
    }
    const int lane = t & 31, wp = t >> 5;
    if (lane == 0) { s1[wp] = sum; s2[wp] = sq; }
    __syncthreads();
    float tot = 0.f, totq = 0.f;
    #pragma unroll
    for (int i = 0; i < 8; i++) { tot += s1[i]; totq += s2[i]; }
    const float mu  = tot * (1.f / 256.f);
    const float var = totq * (1.f / 256.f) - mu * mu;
    const float rs  = rsqrtf(var + 1e-6f);
    const float x2  = (v - mu) * rs * lw[t] + lb[t];

    float pr[10];
    #pragma unroll
    for (int j = 0; j < 10; j++) pr[j] = x2 * wcls[t * 10 + j];
    #pragma unroll
    for (int o = 16; o; o >>= 1)
        #pragma unroll
        for (int j = 0; j < 10; j++) pr[j] += __shfl_xor_sync(FULLMASK, pr[j], o);
    if (lane == 0)
        #pragma unroll
        for (int j = 0; j < 10; j++) sred[wp][j] = pr[j];
    __syncthreads();
    if (t < 10) {
        float s = bcls[t];
        #pragma unroll
        for (int i = 0; i < 8; i++) s += sred[i][t];
        out[(size_t)r * NC_ + t] = s;
    }
}

// ---------------- launch ----------------
extern "C" void kernel_launch(void* const* d_in, const int* in_sizes, int n_in,
                              void* d_out, int out_size)
{
    const float* query  = (const float*)d_in[0];
    const float* value  = (const float*)d_in[1];
    const float* refp   = (const float*)d_in[2];
    const float* w_value= (const float*)d_in[3];
    const float* b_value= (const float*)d_in[4];
    const float* w_off  = (const float*)d_in[5];
    const float* b_off  = (const float*)d_in[6];
    const float* w_attn = (const float*)d_in[7];
    const float* b_attn = (const float*)d_in[8];
    const float* w_out  = (const float*)d_in[9];
    const float* b_out  = (const float*)d_in[10];
    const float* ln1w   = (const float*)d_in[11];
    const float* ln1b   = (const float*)d_in[12];
    const float* w_ffn1 = (const float*)d_in[13];
    const float* b_ffn1 = (const float*)d_in[14];
    const float* w_ffn2 = (const float*)d_in[15];
    const float* b_ffn2 = (const float*)d_in[16];
    const float* ln2w   = (const float*)d_in[17];
    const float* ln2b   = (const float*)d_in[18];
    const float* w_cls  = (const float*)d_in[19];
    const float* b_cls  = (const float*)d_in[20];
    float* out = (float*)d_out;

    float *p_off, *p_attn, *p_featv, *p_feat, *p_x1, *p_h, *p_h2;
    cudaGetSymbolAddress((void**)&p_off,   g_off);
    cudaGetSymbolAddress((void**)&p_attn,  g_attn);
    cudaGetSymbolAddress((void**)&p_featv, g_featv);
    cudaGetSymbolAddress((void**)&p_feat,  g_feat);
    cudaGetSymbolAddress((void**)&p_x1,    g_x1);
    cudaGetSymbolAddress((void**)&p_h,     g_h);
    cudaGetSymbolAddress((void**)&p_h2,    g_h2);

    // 1. query projections (offsets + attn logits)
    gemm64_kernel<false><<<dim3(RT_, 4), 256>>>(query, C_, w_off,  C_,   b_off,  p_off,  C_,   R_, C_);
    gemm64_kernel<false><<<dim3(RT_, 2), 256>>>(query, C_, w_attn, 128,  b_attn, p_attn, 128,  R_, C_);
    // 2. deformable sampling + weighted aggregation of raw value rows
    sample_agg_kernel<<<R_, 256>>>(value, refp);
    // 3. per-head projection through w_value slice (+ wsum * b_value)
    head_gemm_kernel<<<dim3(RT_, 1, M_), 256>>>(w_value, b_value);
    // 4. output projection
    gemm64_kernel<false><<<dim3(RT_, 4), 256>>>(p_featv, C_, w_out, C_,  b_out,  p_feat, C_,   R_, C_);
    // 5. residual + LN1
    ln1_kernel<<<R_, 256>>>(query, ln1w, ln1b);
    // 6. FFN
    gemm64_kernel<true ><<<dim3(RT_, 16), 256>>>(p_x1, C_,  w_ffn1, FFN_, b_ffn1, p_h,  FFN_, R_, C_);
    gemm64_kernel<false><<<dim3(RT_, 4),  256>>>(p_h,  FFN_, w_ffn2, C_,  b_ffn2, p_h2, C_,   R_, FFN_);
    // 7. residual + LN2 + classifier
    ln2_cls_kernel<<<R_, 256>>>(ln2w, ln2b, w_cls, b_cls, out);
}

// round 2
// speedup vs baseline: 1.0261x; 1.0261x over previous
#include <cuda_runtime.h>
#include <math.h>

#define FULLMASK 0xffffffffu

// Problem constants
#define B_    8
#define NQ_   900
#define C_    256
#define M_    8
#define L_    4
#define P_    4
#define D_    32
#define S_    19560
#define FFN_  1024
#define NC_   10
#define R_    (B_*NQ_)            // 7200 rows (b,q)
#define RT128 ((R_ + 127) / 128)  // 57 row tiles

// packed fp32x2 FMA (SASS FFMA2) — PTX-only, ptxas never auto-fuses
#define FMA2(d, a, b, c) asm("fma.rn.f32x2 %0, %1, %2, %3;" \
    : "=l"(d) : "l"(a), "l"(b), "l"(c))
#define PACK2(d, lo, hi) asm("mov.b64 %0, {%1, %2};" : "=l"(d) : "f"(lo), "f"(hi))

__device__ __forceinline__ float f2lo(unsigned long long v) { return __uint_as_float((unsigned)v); }
__device__ __forceinline__ float f2hi(unsigned long long v) { return __uint_as_float((unsigned)(v >> 32)); }

// ---------------- scratch (static device globals; no allocation) ----------------
__device__ float g_off  [R_ * C_];
__device__ float g_attn [R_ * M_ * 16];
__device__ float g_agg  [R_ * M_ * C_];
__device__ float g_wsum [R_ * M_];
__device__ float g_featv[R_ * C_];
__device__ float g_feat [R_ * C_];
__device__ float g_x1   [R_ * C_];
__device__ float g_h    [R_ * FFN_];
__device__ float g_h2   [R_ * C_];

// ---------------- fp32x2 tiled GEMM: C = A[M,K] @ W[K,N] + bias ----------------
// BM=128, BN=64, BK=16, 256 threads, 8x4 microtile via 16 FFMA2 per k-step.
template<bool RELU>
__global__ __launch_bounds__(256) void gemm2_kernel(
    const float* __restrict__ A, int lda,
    const float* __restrict__ W, int ldw,
    const float* __restrict__ bias,
    float* __restrict__ Cout, int ldc,
    int Mrows, int K)
{
    __shared__ float As[16][136];   // transposed: As[k][m]
    __shared__ float Ws[16][68];

    const int tid = threadIdx.x;
    const int tx  = tid & 15;        // col group (4 cols)
    const int ty  = tid >> 4;        // row group (8 rows)
    const int row0 = blockIdx.x * 128, col0 = blockIdx.y * 64;

    // global-load mapping
    const int arow = tid >> 1;            // 0..127
    const int ak   = (tid & 1) << 3;      // 0 or 8
    const int wrow = tid >> 4;            // 0..15
    const int wcol = (tid & 15) << 2;     // 0..60

    const bool avalid = (row0 + arow) < Mrows;
    const float* Abase = A + (size_t)(row0 + arow) * lda + ak;
    const float* Wbase = W + (size_t)wrow * ldw + col0 + wcol;

    unsigned long long acc[4][4];
    #pragma unroll
    for (int i = 0; i < 4; i++)
        #pragma unroll
        for (int j = 0; j < 4; j++) acc[i][j] = 0ull;

    float4 ra0, ra1, rw;
    const float4 f4z = make_float4(0.f, 0.f, 0.f, 0.f);

    // prefetch tile 0
    ra0 = avalid ? *(const float4*)(Abase + 0) : f4z;
    ra1 = avalid ? *(const float4*)(Abase + 4) : f4z;
    rw  = *(const float4*)(Wbase);

    for (int k0 = 0; k0 < K; k0 += 16) {
        // stage registers -> smem
        As[ak + 0][arow] = ra0.x;
        As[ak + 1][arow] = ra0.y;
        As[ak + 2][arow] = ra0.z;
        As[ak + 3][arow] = ra0.w;
        As[ak + 4][arow] = ra1.x;
        As[ak + 5][arow] = ra1.y;
        As[ak + 6][arow] = ra1.z;
        As[ak + 7][arow] = ra1.w;
        *(float4*)&Ws[wrow][wcol] = rw;
        __syncthreads();

        // prefetch next tile (overlaps with compute below)
        if (k0 + 16 < K) {
            ra0 = avalid ? *(const float4*)(Abase + k0 + 16) : f4z;
            ra1 = avalid ? *(const float4*)(Abase + k0 + 20) : f4z;
            rw  = *(const float4*)(Wbase + (size_t)(k0 + 16) * ldw);
        }

        #pragma unroll
        for (int kk = 0; kk < 16; kk++) {
            // 8 A rows as 4 packed fp32 pairs (LDS.128, no movs)
            ulonglong2 ap01 = *(const ulonglong2*)&As[kk][ty << 3];
            ulonglong2 ap23 = *(const ulonglong2*)&As[kk][(ty << 3) + 4];
            float4 w4 = *(const float4*)&Ws[kk][tx << 2];
            unsigned long long wd0, wd1, wd2, wd3;
            PACK2(wd0, w4.x, w4.x);
            PACK2(wd1, w4.y, w4.y);
            PACK2(wd2, w4.z, w4.z);
            PACK2(wd3, w4.w, w4.w);
            unsigned long long ap[4] = {ap01.x, ap01.y, ap23.x, ap23.y};
            unsigned long long wd[4] = {wd0, wd1, wd2, wd3};
            #pragma unroll
            for (int i = 0; i < 4; i++)
                #pragma unroll
                for (int j = 0; j < 4; j++)
                    FMA2(acc[i][j], ap[i], wd[j], acc[i][j]);
        }
        __syncthreads();
    }

    float bv[4];
    #pragma unroll
    for (int j = 0; j < 4; j++) bv[j] = bias[col0 + (tx << 2) + j];

    #pragma unroll
    for (int ip = 0; ip < 4; ip++) {
        const int rlo = row0 + (ty << 3) + (ip << 1);
        float v[2][4];
        #pragma unroll
        for (int j = 0; j < 4; j++) {
            v[0][j] = f2lo(acc[ip][j]) + bv[j];
            v[1][j] = f2hi(acc[ip][j]) + bv[j];
        }
        if (RELU) {
            #pragma unroll
            for (int h = 0; h < 2; h++)
                #pragma unroll
                for (int j = 0; j < 4; j++) v[h][j] = fmaxf(v[h][j], 0.f);
        }
        #pragma unroll
        for (int h = 0; h < 2; h++) {
            const int row = rlo + h;
            if (row < Mrows) {
                float4 o; o.x = v[h][0]; o.y = v[h][1]; o.z = v[h][2]; o.w = v[h][3];
                *(float4*)&Cout[(size_t)row * ldc + col0 + (tx << 2)] = o;
            }
        }
    }
}

// ---------------- per-head projection (fp32x2): featv[r, m*32+n] ----------------
// BM=128, BN=32(=D), BK=16, 256 threads, 8x2 microtile. grid = (57, 1, 8)
__global__ __launch_bounds__(256) void head_gemm2_kernel(
    const float* __restrict__ w_value, const float* __restrict__ b_value)
{
    const int m = blockIdx.z;
    __shared__ float As[16][136];
    __shared__ float Ws[16][36];

    const int tid = threadIdx.x;
    const int tx  = tid & 15;        // col group (2 cols)
    const int ty  = tid >> 4;        // row group (8 rows)
    const int row0 = blockIdx.x * 128;

    const int arow = tid >> 1;
    const int ak   = (tid & 1) << 3;
    const int wrow = tid >> 4;
    const int wcol = (tid & 15) << 1;

    const bool avalid = (row0 + arow) < R_;
    const float* Abase = g_agg + ((size_t)(row0 + arow) * M_ + m) * C_ + ak;
    const float* Wbase = w_value + (size_t)wrow * C_ + m * D_ + wcol;

    unsigned long long acc[4][2];
    #pragma unroll
    for (int i = 0; i < 4; i++) { acc[i][0] = 0ull; acc[i][1] = 0ull; }

    float4 ra0, ra1; float2 rw;
    const float4 f4z = make_float4(0.f, 0.f, 0.f, 0.f);
    ra0 = avalid ? *(const float4*)(Abase + 0) : f4z;
    ra1 = avalid ? *(const float4*)(Abase + 4) : f4z;
    rw  = *(const float2*)(Wbase);

    for (int k0 = 0; k0 < C_; k0 += 16) {
        As[ak + 0][arow] = ra0.x;
        As[ak + 1][arow] = ra0.y;
        As[ak + 2][arow] = ra0.z;
        As[ak + 3][arow] = ra0.w;
        As[ak + 4][arow] = ra1.x;
        As[ak + 5][arow] = ra1.y;
        As[ak + 6][arow] = ra1.z;
        As[ak + 7][arow] = ra1.w;
        *(float2*)&Ws[wrow][wcol] = rw;
        __syncthreads();

        if (k0 + 16 < C_) {
            ra0 = avalid ? *(const float4*)(Abase + k0 + 16) : f4z;
            ra1 = avalid ? *(const float4*)(Abase + k0 + 20) : f4z;
            rw  = *(const float2*)(Wbase + (size_t)(k0 + 16) * C_);
        }

        #pragma unroll
        for (int kk = 0; kk < 16; kk++) {
            ulonglong2 ap01 = *(const ulonglong2*)&As[kk][ty << 3];
            ulonglong2 ap23 = *(const ulonglong2*)&As[kk][(ty << 3) + 4];
            float2 w2 = *(const float2*)&Ws[kk][tx << 1];
            unsigned long long wd0, wd1;
            PACK2(wd0, w2.x, w2.x);
            PACK2(wd1, w2.y, w2.y);
            unsigned long long ap[4] = {ap01.x, ap01.y, ap23.x, ap23.y};
            #pragma unroll
            for (int i = 0; i < 4; i++) {
                FMA2(acc[i][0], ap[i], wd0, acc[i][0]);
                FMA2(acc[i][1], ap[i], wd1, acc[i][1]);
            }
        }
        __syncthreads();
    }

    const float b0 = b_value[m * D_ + (tx << 1) + 0];
    const float b1 = b_value[m * D_ + (tx << 1) + 1];
    #pragma unroll
    for (int ip = 0; ip < 4; ip++) {
        const int rlo = row0 + (ty << 3) + (ip << 1);
        #pragma unroll
        for (int h = 0; h < 2; h++) {
            const int row = rlo + h;
            if (row < R_) {
                const float ws = g_wsum[(size_t)row * M_ + m];
                float2 o;
                o.x = (h ? f2hi(acc[ip][0]) : f2lo(acc[ip][0])) + ws * b0;
                o.y = (h ? f2hi(acc[ip][1]) : f2lo(acc[ip][1])) + ws * b1;
                *(float2*)&g_featv[(size_t)row * C_ + m * D_ + (tx << 1)] = o;
            }
        }
    }
}

// ---------------- deformable sampling + aggregation (unchanged, correct) ----------------
__global__ __launch_bounds__(256) void sample_agg_kernel(
    const float* __restrict__ value, const float* __restrict__ ref_points)
{
    const int r    = blockIdx.x;
    const int b    = r / NQ_;
    const int m    = threadIdx.x >> 5;
    const int lane = threadIdx.x & 31;

    const float rx = ref_points[r * 2 + 0];
    const float ry = ref_points[r * 2 + 1];

    float araw = (lane < 16) ? g_attn[(size_t)r * 128 + m * 16 + lane] : -1e30f;
    float amax = araw;
    #pragma unroll
    for (int o = 8; o; o >>= 1) amax = fmaxf(amax, __shfl_xor_sync(FULLMASK, amax, o, 16));
    float e = (lane < 16) ? __expf(araw - amax) : 0.f;
    float es = e;
    #pragma unroll
    for (int o = 8; o; o >>= 1) es += __shfl_xor_sync(FULLMASK, es, o, 16);
    const float anorm = e / es;

    const float offv = g_off[(size_t)r * C_ + m * 32 + lane];

    float a0[4] = {0.f, 0.f, 0.f, 0.f};
    float a1[4] = {0.f, 0.f, 0.f, 0.f};
    float wsum = 0.f;

    const int Hs[4]  = {92, 46, 23, 12};
    const int Wls[4] = {160, 80, 40, 20};
    const int St[4]  = {0, 14720, 18400, 19320};
    const float* vb = value + (size_t)b * S_ * C_;

#define ACCUM(ptr, wgt) do {                                          \
        const float4* _p4 = (const float4*)(ptr);                     \
        float4 _v0 = _p4[lane];                                       \
        float4 _v1 = _p4[32 + lane];                                  \
        a0[0] = fmaf(wgt, _v0.x, a0[0]);                              \
        a0[1] = fmaf(wgt, _v0.y, a0[1]);                              \
        a0[2] = fmaf(wgt, _v0.z, a0[2]);                              \
        a0[3] = fmaf(wgt, _v0.w, a0[3]);                              \
        a1[0] = fmaf(wgt, _v1.x, a1[0]);                              \
        a1[1] = fmaf(wgt, _v1.y, a1[1]);                              \
        a1[2] = fmaf(wgt, _v1.z, a1[2]);                              \
        a1[3] = fmaf(wgt, _v1.w, a1[3]);                              \
    } while (0)

    #pragma unroll
    for (int l = 0; l < 4; l++) {
        const int Hl = Hs[l], Wl = Wls[l];
        const float invW = 1.f / (float)Wl, invH = 1.f / (float)Hl;
        const float* lb = vb + (size_t)St[l] * C_;
        #pragma unroll
        for (int p = 0; p < 4; p++) {
            const int pt = l * 4 + p;
            const float a  = __shfl_sync(FULLMASK, anorm, pt);
            const float ox = __shfl_sync(FULLMASK, offv, 2 * pt);
            const float oy = __shfl_sync(FULLMASK, offv, 2 * pt + 1);
            const float x = (rx + ox * invW) * (float)Wl - 0.5f;
            const float y = (ry + oy * invH) * (float)Hl - 0.5f;
            const float xf = floorf(x), yf = floorf(y);
            const int   x0 = (int)xf,   y0 = (int)yf;
            const float lx = x - xf,    ly = y - yf;
            const float w00 = a * (1.f - lx) * (1.f - ly);
            const float w01 = a * lx * (1.f - ly);
            const float w10 = a * (1.f - lx) * ly;
            const float w11 = a * lx * ly;
            const bool vx0 = (unsigned)x0       < (unsigned)Wl;
            const bool vx1 = (unsigned)(x0 + 1) < (unsigned)Wl;
            const bool vy0 = (unsigned)y0       < (unsigned)Hl;
            const bool vy1 = (unsigned)(y0 + 1) < (unsigned)Hl;
            if (vy0) {
                const float* rp = lb + (size_t)y0 * Wl * C_;
                if (vx0) { ACCUM(rp + (size_t)x0 * C_,       w00); wsum += w00; }
                if (vx1) { ACCUM(rp + (size_t)(x0 + 1) * C_, w01); wsum += w01; }
            }
            if (vy1) {
                const float* rp = lb + (size_t)(y0 + 1) * Wl * C_;
                if (vx0) { ACCUM(rp + (size_t)x0 * C_,       w10); wsum += w10; }
                if (vx1) { ACCUM(rp + (size_t)(x0 + 1) * C_, w11); wsum += w11; }
            }
        }
    }
#undef ACCUM

    float* ag = g_agg + ((size_t)r * M_ + m) * C_;
    *(float4*)&ag[lane * 4]       = make_float4(a0[0], a0[1], a0[2], a0[3]);
    *(float4*)&ag[128 + lane * 4] = make_float4(a1[0], a1[1], a1[2], a1[3]);
    if (lane == 0) g_wsum[(size_t)r * M_ + m] = wsum;
}

// ---------------- LayerNorm helpers ----------------
__global__ __launch_bounds__(256) void ln1_kernel(
    const float* __restrict__ query,
    const float* __restrict__ lw, const float* __restrict__ lb)
{
    const int r = blockIdx.x, t = threadIdx.x;
    const size_t idx = (size_t)r * C_ + t;
    float v = query[idx] + g_feat[idx];

    __shared__ float s1[8], s2[8];
    float sum = v, sq = v * v;
    #pragma unroll
    for (int o = 16; o; o >>= 1) {
        sum += __shfl_xor_sync(FULLMASK, sum, o);
        sq  += __shfl_xor_sync(FULLMASK, sq, o);
    }
    const int lane = t & 31, wp = t >> 5;
    if (lane == 0) { s1[wp] = sum; s2[wp] = sq; }
    __syncthreads();
    float tot = 0.f, totq = 0.f;
    #pragma unroll
    for (int i = 0; i < 8; i++) { tot += s1[i]; totq += s2[i]; }
    const float mu  = tot * (1.f / 256.f);
    const float var = totq * (1.f / 256.f) - mu * mu;
    const float rs  = rsqrtf(var + 1e-6f);
    g_x1[idx] = (v - mu) * rs * lw[t] + lb[t];
}

__global__ __launch_bounds__(256) void ln2_cls_kernel(
    const float* __restrict__ lw, const float* __restrict__ lb,
    const float* __restrict__ wcls, const float* __restrict__ bcls,
    float* __restrict__ out)
{
    const int r = blockIdx.x, t = threadIdx.x;
    const size_t idx = (size_t)r * C_ + t;
    float v = g_x1[idx] + g_h2[idx];

    __shared__ float s1[8], s2[8];
    __shared__ float sred[8][10];
    float sum = v, sq = v * v;
    #pragma unroll
    for (int o = 16; o; o >>= 1) {
        sum += __shfl_xor_sync(FULLMASK, sum, o);
        sq  += __shfl_xor_sync(FULLMASK, sq, o);
    }
    const int lane = t & 31, wp = t >> 5;
    if (lane == 0) { s1[wp] = sum; s2[wp] = sq; }
    __syncthreads();
    float tot = 0.f, totq = 0.f;
    #pragma unroll
    for (int i = 0; i < 8; i++) { tot += s1[i]; totq += s2[i]; }
    const float mu  = tot * (1.f / 256.f);
    const float var = totq * (1.f / 256.f) - mu * mu;
    const float rs  = rsqrtf(var + 1e-6f);
    const float x2  = (v - mu) * rs * lw[t] + lb[t];

    float pr[10];
    #pragma unroll
    for (int j = 0; j < 10; j++) pr[j] = x2 * wcls[t * 10 + j];
    #pragma unroll
    for (int o = 16; o; o >>= 1)
        #pragma unroll
        for (int j = 0; j < 10; j++) pr[j] += __shfl_xor_sync(FULLMASK, pr[j], o);
    if (lane == 0)
        #pragma unroll
        for (int j = 0; j < 10; j++) sred[wp][j] = pr[j];
    __syncthreads();
    if (t < 10) {
        float s = bcls[t];
        #pragma unroll
        for (int i = 0; i < 8; i++) s += sred[i][t];
        out[(size_t)r * NC_ + t] = s;
    }
}

// ---------------- launch ----------------
extern "C" void kernel_launch(void* const* d_in, const int* in_sizes, int n_in,
                              void* d_out, int out_size)
{
    const float* query  = (const float*)d_in[0];
    const float* value  = (const float*)d_in[1];
    const float* refp   = (const float*)d_in[2];
    const float* w_value= (const float*)d_in[3];
    const float* b_value= (const float*)d_in[4];
    const float* w_off  = (const float*)d_in[5];
    const float* b_off  = (const float*)d_in[6];
    const float* w_attn = (const float*)d_in[7];
    const float* b_attn = (const float*)d_in[8];
    const float* w_out  = (const float*)d_in[9];
    const float* b_out  = (const float*)d_in[10];
    const float* ln1w   = (const float*)d_in[11];
    const float* ln1b   = (const float*)d_in[12];
    const float* w_ffn1 = (const float*)d_in[13];
    const float* b_ffn1 = (const float*)d_in[14];
    const float* w_ffn2 = (const float*)d_in[15];
    const float* b_ffn2 = (const float*)d_in[16];
    const float* ln2w   = (const float*)d_in[17];
    const float* ln2b   = (const float*)d_in[18];
    const float* w_cls  = (const float*)d_in[19];
    const float* b_cls  = (const float*)d_in[20];
    float* out = (float*)d_out;

    float *p_off, *p_attn, *p_featv, *p_feat, *p_x1, *p_h, *p_h2;
    cudaGetSymbolAddress((void**)&p_off,   g_off);
    cudaGetSymbolAddress((void**)&p_attn,  g_attn);
    cudaGetSymbolAddress((void**)&p_featv, g_featv);
    cudaGetSymbolAddress((void**)&p_feat,  g_feat);
    cudaGetSymbolAddress((void**)&p_x1,    g_x1);
    cudaGetSymbolAddress((void**)&p_h,     g_h);
    cudaGetSymbolAddress((void**)&p_h2,    g_h2);

    // 1. query projections (offsets + attn logits)
    gemm2_kernel<false><<<dim3(RT128, 4), 256>>>(query, C_, w_off,  C_,   b_off,  p_off,  C_,   R_, C_);
    gemm2_kernel<false><<<dim3(RT128, 2), 256>>>(query, C_, w_attn, 128,  b_attn, p_attn, 128,  R_, C_);
    // 2. deformable sampling + weighted aggregation of raw value rows
    sample_agg_kernel<<<R_, 256>>>(value, refp);
    // 3. per-head projection through w_value slice (+ wsum * b_value)
    head_gemm2_kernel<<<dim3(RT128, 1, M_), 256>>>(w_value, b_value);
    // 4. output projection
    gemm2_kernel<false><<<dim3(RT128, 4), 256>>>(p_featv, C_, w_out, C_,  b_out,  p_feat, C_,   R_, C_);
    // 5. residual + LN1
    ln1_kernel<<<R_, 256>>>(query, ln1w, ln1b);
    // 6. FFN
    gemm2_kernel<true ><<<dim3(RT128, 16), 256>>>(p_x1, C_,  w_ffn1, FFN_, b_ffn1, p_h,  FFN_, R_, C_);
    gemm2_kernel<false><<<dim3(RT128, 4),  256>>>(p_h,  FFN_, w_ffn2, C_,  b_ffn2, p_h2, C_,   R_, FFN_);
    // 7. residual + LN2 + classifier
    ln2_cls_kernel<<<R_, 256>>>(ln2w, ln2b, w_cls, b_cls, out);
}

// round 4
// speedup vs baseline: 1.2891x; 1.2562x over previous
#include <cuda_runtime.h>
#include <math.h>
#include <stdint.h>

#define FULLMASK 0xffffffffu

// Problem constants
#define B_    8
#define NQ_   900
#define C_    256
#define M_    8
#define D_    32
#define S_    19560
#define FFN_  1024
#define NC_   10
#define R_    (B_*NQ_)            // 7200 rows
#define MT_   ((R_ + 127) / 128)  // 57 M tiles

// ---------------- scratch (static device globals) ----------------
__device__ float g_qout [R_ * 384];        // [off(256) | attn(128)] per row
__device__ float g_agg  [R_ * M_ * C_];    // [7200][2048]
__device__ float g_wsum [R_ * M_];
__device__ float g_featv[R_ * C_];
__device__ float g_feat [R_ * C_];
__device__ float g_x1   [R_ * C_];
__device__ float g_h    [R_ * FFN_];
__device__ float g_h2   [R_ * C_];
// transposed weights [N, K]
__device__ float g_wqT  [384 * 256];
__device__ float g_bq   [384];
__device__ float g_woutT[256 * 256];
__device__ float g_f1T  [1024 * 256];
__device__ float g_f2T  [256 * 1024];
__device__ float g_wblkT[256 * 1024];      // block-diag value proj, K-windowed

__device__ __forceinline__ uint32_t tf32cvt(float f) {
    uint32_t u; asm("cvt.rna.tf32.f32 %0, %1;" : "=r"(u) : "f"(f)); return u;
}

// tf32 m16n8k8 warp MMA (sm_80+ PTX, no arch-suffix gating)
#define MMA_TF32(c, a, b) \
    asm volatile("mma.sync.aligned.m16n8k8.row.col.f32.tf32.tf32.f32 " \
        "{%0,%1,%2,%3}, {%4,%5,%6,%7}, {%8,%9}, {%0,%1,%2,%3};" \
        : "+f"((c)[0]), "+f"((c)[1]), "+f"((c)[2]), "+f"((c)[3]) \
        : "r"((a)[0]), "r"((a)[1]), "r"((a)[2]), "r"((a)[3]), \
          "r"((b)[0]), "r"((b)[1]))

// ---------------- weight prep: transposes + concat + block-diag ----------------
__global__ __launch_bounds__(256) void prep_weights(
    const float* __restrict__ w_off, const float* __restrict__ w_attn,
    const float* __restrict__ b_off, const float* __restrict__ b_attn,
    const float* __restrict__ w_out_, const float* __restrict__ w_ffn1,
    const float* __restrict__ w_ffn2, const float* __restrict__ w_value)
{
    int idx = blockIdx.x * 256 + threadIdx.x;
    if (idx < 98304) {                                   // wqT [384,256]
        int n = idx >> 8, k = idx & 255;
        g_wqT[idx] = (n < 256) ? w_off[k * 256 + n] : w_attn[k * 128 + (n - 256)];
        if (idx < 384) g_bq[idx] = (idx < 256) ? b_off[idx] : b_attn[idx - 256];
        return;
    }
    idx -= 98304;
    if (idx < 65536) {                                   // woutT [256,256]
        int n = idx >> 8, k = idx & 255;
        g_woutT[idx] = w_out_[k * 256 + n];
        return;
    }
    idx -= 65536;
    if (idx < 262144) {                                  // f1T [1024,256]
        int n = idx >> 8, k = idx & 255;
        g_f1T[idx] = w_ffn1[k * 1024 + n];
        return;
    }
    idx -= 262144;
    if (idx < 262144) {                                  // f2T [256,1024]
        int n = idx >> 10, k = idx & 1023;
        g_f2T[idx] = w_ffn2[k * 256 + n];
        return;
    }
    idx -= 262144;
    if (idx < 262144) {                                  // wblkT [256,1024] (K-window per N-tile)
        int n = idx >> 10, j = idx & 1023;
        g_wblkT[idx] = ((j >> 8) == ((n & 127) >> 5)) ? w_value[(j & 255) * 256 + n] : 0.f;
        return;
    }
}

// ---------------- tf32 mma.sync GEMM: C[Mrows,N] = A @ WT^T + epilogue ----------------
// EPI: 0 = +bias, 1 = relu(+bias), 2 = +wsum[row,head]*bias
// CTA 128x128, 8 warps (2M x 4N), warp tile 64x32, BK=16, double-buffered smem.
template<int EPI>
__global__ __launch_bounds__(256) void gemm_mma(
    const float* __restrict__ A, int lda, int kstride,
    const float* __restrict__ WT, int ldb,
    const float* __restrict__ bias, const float* __restrict__ wsum,
    float* __restrict__ Cg, int ldc, int Mrows, int Klen)
{
    __shared__ float As[2][128][20];
    __shared__ float Bs[2][128][20];

    const int tid  = threadIdx.x;
    const int wid  = tid >> 5, lane = tid & 31;
    const int g    = lane >> 2, tg = lane & 3;
    const int wm0  = (wid & 1) << 6;     // 0 or 64
    const int wn0  = (wid >> 1) << 5;    // 0,32,64,96
    const int m0   = blockIdx.x * 128;
    const int n0   = blockIdx.y * 128;

    // global-load mapping: 2 float4 per tensor per thread per BK
    const int arow = tid >> 1;
    const int aq   = (tid & 1) << 3;     // 0 or 8
    const bool av  = (m0 + arow) < Mrows;
    const float* ap = A  + (size_t)(m0 + arow) * lda + (size_t)blockIdx.y * kstride + aq;
    const float* bp = WT + (size_t)(n0 + arow) * ldb + aq;

    float acc[4][4][4];
    #pragma unroll
    for (int i = 0; i < 4; i++)
        #pragma unroll
        for (int j = 0; j < 4; j++)
            #pragma unroll
            for (int v = 0; v < 4; v++) acc[i][j][v] = 0.f;

    const float4 z4 = make_float4(0.f, 0.f, 0.f, 0.f);
    float4 ra0, ra1, rb0, rb1;
    ra0 = av ? *(const float4*)(ap)     : z4;
    ra1 = av ? *(const float4*)(ap + 4) : z4;
    rb0 = *(const float4*)(bp);
    rb1 = *(const float4*)(bp + 4);

    const int niter = Klen >> 4;
    for (int it = 0; it < niter; it++) {
        const int s = it & 1;
        // store prefetched regs (tf32-rounded) to smem
        uint4 ua, ub;
        ua.x = tf32cvt(ra0.x); ua.y = tf32cvt(ra0.y); ua.z = tf32cvt(ra0.z); ua.w = tf32cvt(ra0.w);
        *(uint4*)&As[s][arow][aq] = ua;
        ua.x = tf32cvt(ra1.x); ua.y = tf32cvt(ra1.y); ua.z = tf32cvt(ra1.z); ua.w = tf32cvt(ra1.w);
        *(uint4*)&As[s][arow][aq + 4] = ua;
        ub.x = tf32cvt(rb0.x); ub.y = tf32cvt(rb0.y); ub.z = tf32cvt(rb0.z); ub.w = tf32cvt(rb0.w);
        *(uint4*)&Bs[s][arow][aq] = ub;
        ub.x = tf32cvt(rb1.x); ub.y = tf32cvt(rb1.y); ub.z = tf32cvt(rb1.z); ub.w = tf32cvt(rb1.w);
        *(uint4*)&Bs[s][arow][aq + 4] = ub;
        __syncthreads();

        // prefetch next BK while computing this one
        if (it + 1 < niter) {
            const int k0 = (it + 1) << 4;
            ra0 = av ? *(const float4*)(ap + k0)     : z4;
            ra1 = av ? *(const float4*)(ap + k0 + 4) : z4;
            rb0 = *(const float4*)(bp + k0);
            rb1 = *(const float4*)(bp + k0 + 4);
        }

        #pragma unroll
        for (int ks = 0; ks < 16; ks += 8) {
            uint32_t af[4][4], bf[4][2];
            #pragma unroll
            for (int i = 0; i < 4; i++) {
                const int r0 = wm0 + (i << 4) + g;
                af[i][0] = __float_as_uint(As[s][r0    ][ks + tg]);
                af[i][1] = __float_as_uint(As[s][r0 + 8][ks + tg]);
                af[i][2] = __float_as_uint(As[s][r0    ][ks + tg + 4]);
                af[i][3] = __float_as_uint(As[s][r0 + 8][ks + tg + 4]);
            }
            #pragma unroll
            for (int j = 0; j < 4; j++) {
                const int c0 = wn0 + (j << 3) + g;
                bf[j][0] = __float_as_uint(Bs[s][c0][ks + tg]);
                bf[j][1] = __float_as_uint(Bs[s][c0][ks + tg + 4]);
            }
            #pragma unroll
            for (int i = 0; i < 4; i++)
                #pragma unroll
                for (int j = 0; j < 4; j++)
                    MMA_TF32(acc[i][j], af[i], bf[j]);
        }
        // one sync per iter is sufficient: compute(it) finishes before sync(it+1),
        // and the next write to this stage happens only at it+2, after that sync.
        __syncthreads();
    }

    // epilogue: direct float2 stores, c-fragment layout
    #pragma unroll
    for (int j = 0; j < 4; j++) {
        const int col = n0 + wn0 + (j << 3) + (tg << 1);
        const float2 bv = *(const float2*)&bias[col];
        #pragma unroll
        for (int i = 0; i < 4; i++) {
            const int row0 = m0 + wm0 + (i << 4) + g;
            const int row1 = row0 + 8;
            float2 v0 = make_float2(acc[i][j][0], acc[i][j][1]);
            float2 v1 = make_float2(acc[i][j][2], acc[i][j][3]);
            if (EPI == 0) {
                v0.x += bv.x; v0.y += bv.y; v1.x += bv.x; v1.y += bv.y;
            } else if (EPI == 1) {
                v0.x = fmaxf(v0.x + bv.x, 0.f); v0.y = fmaxf(v0.y + bv.y, 0.f);
                v1.x = fmaxf(v1.x + bv.x, 0.f); v1.y = fmaxf(v1.y + bv.y, 0.f);
            }
            if (row0 < Mrows) {
                if (EPI == 2) {
                    const float ws = wsum[(size_t)row0 * 8 + (col >> 5)];
                    v0.x += ws * bv.x; v0.y += ws * bv.y;
                }
                *(float2*)&Cg[(size_t)row0 * ldc + col] = v0;
            }
            if (row1 < Mrows) {
                if (EPI == 2) {
                    const float ws = wsum[(size_t)row1 * 8 + (col >> 5)];
                    v1.x += ws * bv.x; v1.y += ws * bv.y;
                }
                *(float2*)&Cg[(size_t)row1 * ldc + col] = v1;
            }
        }
    }
}

// ---------------- deformable sampling + aggregation ----------------
__global__ __launch_bounds__(256) void sample_agg_kernel(
    const float* __restrict__ value, const float* __restrict__ ref_points)
{
    const int r    = blockIdx.x;
    const int b    = r / NQ_;
    const int m    = threadIdx.x >> 5;
    const int lane = threadIdx.x & 31;

    const float rx = ref_points[r * 2 + 0];
    const float ry = ref_points[r * 2 + 1];

    float araw = (lane < 16) ? g_qout[(size_t)r * 384 + 256 + m * 16 + lane] : -1e30f;
    float amax = araw;
    #pragma unroll
    for (int o = 8; o; o >>= 1) amax = fmaxf(amax, __shfl_xor_sync(FULLMASK, amax, o, 16));
    float e = (lane < 16) ? __expf(araw - amax) : 0.f;
    float es = e;
    #pragma unroll
    for (int o = 8; o; o >>= 1) es += __shfl_xor_sync(FULLMASK, es, o, 16);
    const float anorm = e / es;

    const float offv = g_qout[(size_t)r * 384 + m * 32 + lane];

    float a0[4] = {0.f, 0.f, 0.f, 0.f};
    float a1[4] = {0.f, 0.f, 0.f, 0.f};
    float wsum = 0.f;

    const int Hs[4]  = {92, 46, 23, 12};
    const int Wls[4] = {160, 80, 40, 20};
    const int St[4]  = {0, 14720, 18400, 19320};
    const float* vb = value + (size_t)b * S_ * C_;

#define ACCUM(ptr, wgt) do {                                          \
        const float4* _p4 = (const float4*)(ptr);                     \
        float4 _v0 = _p4[lane];                                       \
        float4 _v1 = _p4[32 + lane];                                  \
        a0[0] = fmaf(wgt, _v0.x, a0[0]);                              \
        a0[1] = fmaf(wgt, _v0.y, a0[1]);                              \
        a0[2] = fmaf(wgt, _v0.z, a0[2]);                              \
        a0[3] = fmaf(wgt, _v0.w, a0[3]);                              \
        a1[0] = fmaf(wgt, _v1.x, a1[0]);                              \
        a1[1] = fmaf(wgt, _v1.y, a1[1]);                              \
        a1[2] = fmaf(wgt, _v1.z, a1[2]);                              \
        a1[3] = fmaf(wgt, _v1.w, a1[3]);                              \
    } while (0)

    #pragma unroll
    for (int l = 0; l < 4; l++) {
        const int Hl = Hs[l], Wl = Wls[l];
        const float invW = 1.f / (float)Wl, invH = 1.f / (float)Hl;
        const float* lb = vb + (size_t)St[l] * C_;
        #pragma unroll
        for (int p = 0; p < 4; p++) {
            const int pt = l * 4 + p;
            const float a  = __shfl_sync(FULLMASK, anorm, pt);
            const float ox = __shfl_sync(FULLMASK, offv, 2 * pt);
            const float oy = __shfl_sync(FULLMASK, offv, 2 * pt + 1);
            const float x = (rx + ox * invW) * (float)Wl - 0.5f;
            const float y = (ry + oy * invH) * (float)Hl - 0.5f;
            const float xf = floorf(x), yf = floorf(y);
            const int   x0 = (int)xf,   y0 = (int)yf;
            const float lx = x - xf,    ly = y - yf;
            const float w00 = a * (1.f - lx) * (1.f - ly);
            const float w01 = a * lx * (1.f - ly);
            const float w10 = a * (1.f - lx) * ly;
            const float w11 = a * lx * ly;
            const bool vx0 = (unsigned)x0       < (unsigned)Wl;
            const bool vx1 = (unsigned)(x0 + 1) < (unsigned)Wl;
            const bool vy0 = (unsigned)y0       < (unsigned)Hl;
            const bool vy1 = (unsigned)(y0 + 1) < (unsigned)Hl;
            if (vy0) {
                const float* rp = lb + (size_t)y0 * Wl * C_;
                if (vx0) { ACCUM(rp + (size_t)x0 * C_,       w00); wsum += w00; }
                if (vx1) { ACCUM(rp + (size_t)(x0 + 1) * C_, w01); wsum += w01; }
            }
            if (vy1) {
                const float* rp = lb + (size_t)(y0 + 1) * Wl * C_;
                if (vx0) { ACCUM(rp + (size_t)x0 * C_,       w10); wsum += w10; }
                if (vx1) { ACCUM(rp + (size_t)(x0 + 1) * C_, w11); wsum += w11; }
            }
        }
    }
#undef ACCUM

    float* ag = g_agg + ((size_t)r * M_ + m) * C_;
    *(float4*)&ag[lane * 4]       = make_float4(a0[0], a0[1], a0[2], a0[3]);
    *(float4*)&ag[128 + lane * 4] = make_float4(a1[0], a1[1], a1[2], a1[3]);
    if (lane == 0) g_wsum[(size_t)r * M_ + m] = wsum;
}

// ---------------- LayerNorm helpers ----------------
__global__ __launch_bounds__(256) void ln1_kernel(
    const float* __restrict__ query,
    const float* __restrict__ lw, const float* __restrict__ lb)
{
    const int r = blockIdx.x, t = threadIdx.x;
    const size_t idx = (size_t)r * C_ + t;
    float v = query[idx] + g_feat[idx];

    __shared__ float s1[8], s2[8];
    float sum = v, sq = v * v;
    #pragma unroll
    for (int o = 16; o; o >>= 1) {
        sum += __shfl_xor_sync(FULLMASK, sum, o);
        sq  += __shfl_xor_sync(FULLMASK, sq, o);
    }
    const int lane = t & 31, wp = t >> 5;
    if (lane == 0) { s1[wp] = sum; s2[wp] = sq; }
    __syncthreads();
    float tot = 0.f, totq = 0.f;
    #pragma unroll
    for (int i = 0; i < 8; i++) { tot += s1[i]; totq += s2[i]; }
    const float mu  = tot * (1.f / 256.f);
    const float var = totq * (1.f / 256.f) - mu * mu;
    const float rs  = rsqrtf(var + 1e-6f);
    g_x1[idx] = (v - mu) * rs * lw[t] + lb[t];
}

__global__ __launch_bounds__(256) void ln2_cls_kernel(
    const float* __restrict__ lw, const float* __restrict__ lb,
    const float* __restrict__ wcls, const float* __restrict__ bcls,
    float* __restrict__ out)
{
    const int r = blockIdx.x, t = threadIdx.x;
    const size_t idx = (size_t)r * C_ + t;
    float v = g_x1[idx] + g_h2[idx];

    __shared__ float s1[8], s2[8];
    __shared__ float sred[8][10];
    float sum = v, sq = v * v;
    #pragma unroll
    for (int o = 16; o; o >>= 1) {
        sum += __shfl_xor_sync(FULLMASK, sum, o);
        sq  += __shfl_xor_sync(FULLMASK, sq, o);
    }
    const int lane = t & 31, wp = t >> 5;
    if (lane == 0) { s1[wp] = sum; s2[wp] = sq; }
    __syncthreads();
    float tot = 0.f, totq = 0.f;
    #pragma unroll
    for (int i = 0; i < 8; i++) { tot += s1[i]; totq += s2[i]; }
    const float mu  = tot * (1.f / 256.f);
    const float var = totq * (1.f / 256.f) - mu * mu;
    const float rs  = rsqrtf(var + 1e-6f);
    const float x2  = (v - mu) * rs * lw[t] + lb[t];

    float pr[10];
    #pragma unroll
    for (int j = 0; j < 10; j++) pr[j] = x2 * wcls[t * 10 + j];
    #pragma unroll
    for (int o = 16; o; o >>= 1)
        #pragma unroll
        for (int j = 0; j < 10; j++) pr[j] += __shfl_xor_sync(FULLMASK, pr[j], o);
    if (lane == 0)
        #pragma unroll
        for (int j = 0; j < 10; j++) sred[wp][j] = pr[j];
    __syncthreads();
    if (t < 10) {
        float s = bcls[t];
        #pragma unroll
        for (int i = 0; i < 8; i++) s += sred[i][t];
        out[(size_t)r * NC_ + t] = s;
    }
}

// ---------------- launch ----------------
extern "C" void kernel_launch(void* const* d_in, const int* in_sizes, int n_in,
                              void* d_out, int out_size)
{
    const float* query  = (const float*)d_in[0];
    const float* value  = (const float*)d_in[1];
    const float* refp   = (const float*)d_in[2];
    const float* w_value= (const float*)d_in[3];
    const float* b_value= (const float*)d_in[4];
    const float* w_off  = (const float*)d_in[5];
    const float* b_off  = (const float*)d_in[6];
    const float* w_attn = (const float*)d_in[7];
    const float* b_attn = (const float*)d_in[8];
    const float* w_out  = (const float*)d_in[9];
    const float* b_out  = (const float*)d_in[10];
    const float* ln1w   = (const float*)d_in[11];
    const float* ln1b   = (const float*)d_in[12];
    const float* w_ffn1 = (const float*)d_in[13];
    const float* b_ffn1 = (const float*)d_in[14];
    const float* w_ffn2 = (const float*)d_in[15];
    const float* b_ffn2 = (const float*)d_in[16];
    const float* ln2w   = (const float*)d_in[17];
    const float* ln2b   = (const float*)d_in[18];
    const float* w_cls  = (const float*)d_in[19];
    const float* b_cls  = (const float*)d_in[20];
    float* out = (float*)d_out;

    float *p_qout, *p_agg, *p_wsum, *p_featv, *p_feat, *p_x1, *p_h, *p_h2;
    float *p_wqT, *p_bq, *p_woutT, *p_f1T, *p_f2T, *p_wblkT;
    cudaGetSymbolAddress((void**)&p_qout,  g_qout);
    cudaGetSymbolAddress((void**)&p_agg,   g_agg);
    cudaGetSymbolAddress((void**)&p_wsum,  g_wsum);
    cudaGetSymbolAddress((void**)&p_featv, g_featv);
    cudaGetSymbolAddress((void**)&p_feat,  g_feat);
    cudaGetSymbolAddress((void**)&p_x1,    g_x1);
    cudaGetSymbolAddress((void**)&p_h,     g_h);
    cudaGetSymbolAddress((void**)&p_h2,    g_h2);
    cudaGetSymbolAddress((void**)&p_wqT,   g_wqT);
    cudaGetSymbolAddress((void**)&p_bq,    g_bq);
    cudaGetSymbolAddress((void**)&p_woutT, g_woutT);
    cudaGetSymbolAddress((void**)&p_f1T,   g_f1T);
    cudaGetSymbolAddress((void**)&p_f2T,   g_f2T);
    cudaGetSymbolAddress((void**)&p_wblkT, g_wblkT);

    // 0. weight prep (transpose / concat / block-diag)
    prep_weights<<<3712, 256>>>(w_off, w_attn, b_off, b_attn, w_out, w_ffn1, w_ffn2, w_value);
    // 1. fused query projection: [off | attn] = query @ [w_off | w_attn]
    gemm_mma<0><<<dim3(MT_, 3), 256>>>(query, C_, 0, p_wqT, 256, p_bq, nullptr,
                                       p_qout, 384, R_, 256);
    // 2. deformable sampling + weighted aggregation of raw value rows
    sample_agg_kernel<<<R_, 256>>>(value, refp);
    // 3. per-head value projection (block-diag GEMM, K-window 1024 per N-tile)
    gemm_mma<2><<<dim3(MT_, 2), 256>>>(p_agg, 2048, 1024, p_wblkT, 1024, b_value,
                                       p_wsum, p_featv, C_, R_, 1024);
    // 4. output projection
    gemm_mma<0><<<dim3(MT_, 2), 256>>>(p_featv, C_, 0, p_woutT, 256, b_out, nullptr,
                                       p_feat, C_, R_, 256);
    // 5. residual + LN1
    ln1_kernel<<<R_, 256>>>(query, ln1w, ln1b);
    // 6. FFN
    gemm_mma<1><<<dim3(MT_, 8), 256>>>(p_x1, C_, 0, p_f1T, 256, b_ffn1, nullptr,
                                       p_h, FFN_, R_, 256);
    gemm_mma<0><<<dim3(MT_, 2), 256>>>(p_h, FFN_, 0, p_f2T, 1024, b_ffn2, nullptr,
                                       p_h2, C_, R_, 1024);
    // 7. residual + LN2 + classifier
    ln2_cls_kernel<<<R_, 256>>>(ln2w, ln2b, w_cls, b_cls, out);
}

// round 5
// speedup vs baseline: 1.4532x; 1.1273x over previous
#include <cuda_runtime.h>
#include <math.h>
#include <stdint.h>

#define FULLMASK 0xffffffffu

// Problem constants
#define B_    8
#define NQ_   900
#define C_    256
#define M_    8
#define D_    32
#define S_    19560
#define FFN_  1024
#define NC_   10
#define R_    (B_*NQ_)            // 7200 rows
#define MT_   ((R_ + 127) / 128)  // 57 M tiles

// ---------------- scratch (static device globals) ----------------
__device__ float g_qout [R_ * 384];        // [off(256) | attn(128)] per row
__device__ float g_agg  [R_ * M_ * C_];    // [7200][2048]
__device__ float g_wsum [R_ * M_];
__device__ float g_featv[R_ * C_];
__device__ float g_feat [R_ * C_];
__device__ float g_x1   [R_ * C_];
__device__ float g_h    [R_ * FFN_];
__device__ float g_h2   [R_ * C_];
// transposed weights [N, K]
__device__ float g_wqT  [384 * 256];
__device__ float g_bq   [384];
__device__ float g_woutT[256 * 256];
__device__ float g_f1T  [1024 * 256];
__device__ float g_f2T  [256 * 1024];
__device__ float g_wvT  [M_ * D_ * 256];   // per-head value-proj slice [8][32][256]

__device__ __forceinline__ uint32_t tf32cvt(float f) {
    uint32_t u; asm("cvt.rna.tf32.f32 %0, %1;" : "=r"(u) : "f"(f)); return u;
}

#define MMA_TF32(c, a, b) \
    asm volatile("mma.sync.aligned.m16n8k8.row.col.f32.tf32.tf32.f32 " \
        "{%0,%1,%2,%3}, {%4,%5,%6,%7}, {%8,%9}, {%0,%1,%2,%3};" \
        : "+f"((c)[0]), "+f"((c)[1]), "+f"((c)[2]), "+f"((c)[3]) \
        : "r"((a)[0]), "r"((a)[1]), "r"((a)[2]), "r"((a)[3]), \
          "r"((b)[0]), "r"((b)[1]))

#define CP_ASYNC16(saddr, gaddr, srcsz) \
    asm volatile("cp.async.cg.shared.global [%0], [%1], 16, %2;" \
        :: "r"(saddr), "l"(gaddr), "r"(srcsz))
#define CP_COMMIT()  asm volatile("cp.async.commit_group;" ::: "memory")
#define CP_WAIT2()   asm volatile("cp.async.wait_group 2;" ::: "memory")

// ---------------- weight prep ----------------
__global__ __launch_bounds__(256) void prep_weights(
    const float* __restrict__ w_off, const float* __restrict__ w_attn,
    const float* __restrict__ b_off, const float* __restrict__ b_attn,
    const float* __restrict__ w_out_, const float* __restrict__ w_ffn1,
    const float* __restrict__ w_ffn2, const float* __restrict__ w_value)
{
    int idx = blockIdx.x * 256 + threadIdx.x;
    if (idx < 98304) {                                   // wqT [384,256]
        int n = idx >> 8, k = idx & 255;
        g_wqT[idx] = (n < 256) ? w_off[k * 256 + n] : w_attn[k * 128 + (n - 256)];
        if (idx < 384) g_bq[idx] = (idx < 256) ? b_off[idx] : b_attn[idx - 256];
        return;
    }
    idx -= 98304;
    if (idx < 65536) {                                   // woutT [256,256]
        int n = idx >> 8, k = idx & 255;
        g_woutT[idx] = w_out_[k * 256 + n];
        return;
    }
    idx -= 65536;
    if (idx < 262144) {                                  // f1T [1024,256]
        int n = idx >> 8, k = idx & 255;
        g_f1T[idx] = w_ffn1[k * 1024 + n];
        return;
    }
    idx -= 262144;
    if (idx < 262144) {                                  // f2T [256,1024]
        int n = idx >> 10, k = idx & 1023;
        g_f2T[idx] = w_ffn2[k * 256 + n];
        return;
    }
    idx -= 262144;
    if (idx < 65536) {                                   // wvT [8][32][256]
        int m = idx >> 13, n = (idx >> 8) & 31, k = idx & 255;
        g_wvT[idx] = w_value[k * 256 + m * 32 + n];
        return;
    }
}

// ---------------- tf32 mma GEMM w/ cp.async 4-stage pipeline ----------------
// C[Mrows, gridDim.y*BN (per z)] = A @ WT^T + epilogue
// BM=128, 8 warps as 4(M) x 2(N); warp tile 32 x BN/2.
// EPI: 0 = +bias, 1 = relu(+bias), 2 = +wsum[row, z]*bias
template<int BN, int EPI>
__global__ __launch_bounds__(256) void gemm_cp(
    const float* __restrict__ A, int lda, int zA,
    const float* __restrict__ WT, int ldb, int zB,
    const float* __restrict__ bias, int zbias,
    const float* __restrict__ wsum,
    float* __restrict__ Cg, int ldc, int zC,
    int Mrows, int Klen)
{
    constexpr int WN = BN / 2;
    constexpr int NJ = WN / 8;
    extern __shared__ float smp[];
    float* As = smp;                    // [4][128][20]
    float* Bs = smp + 4 * 128 * 20;     // [4][BN][20]
#define ASA(s,r,c) As[(((s) << 7) + (r)) * 20 + (c)]
#define BSA(s,r,c) Bs[((s) * BN + (r)) * 20 + (c)]

    const int tid  = threadIdx.x;
    const int wid  = tid >> 5, lane = tid & 31;
    const int g    = lane >> 2, tg = lane & 3;
    const int wm   = (wid & 3) << 5;      // 0,32,64,96
    const int wn   = (wid >> 2) * WN;     // 0 or WN
    const int m0   = blockIdx.x * 128;
    const int n0   = blockIdx.y * BN;
    const int z    = blockIdx.z;

    A    += (size_t)z * zA;
    WT   += (size_t)z * zB;
    bias += z * zbias;

    // load mapping
    const int ar  = tid >> 1;                 // A row 0..127
    const int ac  = (tid & 1) << 3;           // A col 0 or 8
    const int br  = tid >> 2;                 // B row 0..63
    const int bc  = (tid & 3) << 2;           // B col 0,4,8,12
    const uint32_t aval = ((m0 + ar) < Mrows) ? 16u : 0u;
    const bool bldr = (BN == 64) || (tid < 128);
    const float* agp = A  + (size_t)(m0 + ar) * lda + ac;
    const float* bgp = WT + (size_t)(n0 + br) * ldb + bc;

    const int niter = Klen >> 4;

    // issue loads for k-block kb into stage s
    auto issue = [&](int kb, int s) {
        uint32_t sa = (uint32_t)__cvta_generic_to_shared(&ASA(s, ar, ac));
        CP_ASYNC16(sa,      agp + (kb << 4),     aval);
        CP_ASYNC16(sa + 16, agp + (kb << 4) + 4, aval);
        if (bldr) {
            uint32_t sb = (uint32_t)__cvta_generic_to_shared(&BSA(s, br, bc));
            CP_ASYNC16(sb, bgp + (kb << 4), 16u);
        }
    };

    float acc[2][NJ][4];
    #pragma unroll
    for (int i = 0; i < 2; i++)
        #pragma unroll
        for (int j = 0; j < NJ; j++)
            #pragma unroll
            for (int v = 0; v < 4; v++) acc[i][j][v] = 0.f;

    // prologue: stages 0..2
    issue(0, 0); CP_COMMIT();
    issue(1, 1); CP_COMMIT();
    issue(2, 2); CP_COMMIT();

    for (int it = 0; it < niter; it++) {
        const int s = it & 3;
        CP_WAIT2();
        __syncthreads();
        // issue next (stage (it+3)&3 was consumed at it-1; sync above protects it)
        if (it + 3 < niter) issue(it + 3, (it + 3) & 3);
        CP_COMMIT();

        #pragma unroll
        for (int ks = 0; ks < 16; ks += 8) {
            uint32_t af[2][4], bf[NJ][2];
            #pragma unroll
            for (int mi = 0; mi < 2; mi++) {
                const int r0 = wm + (mi << 4) + g;
                af[mi][0] = tf32cvt(ASA(s, r0,     ks + tg));
                af[mi][1] = tf32cvt(ASA(s, r0 + 8, ks + tg));
                af[mi][2] = tf32cvt(ASA(s, r0,     ks + tg + 4));
                af[mi][3] = tf32cvt(ASA(s, r0 + 8, ks + tg + 4));
            }
            #pragma unroll
            for (int nj = 0; nj < NJ; nj++) {
                const int c0 = wn + (nj << 3) + g;
                bf[nj][0] = tf32cvt(BSA(s, c0, ks + tg));
                bf[nj][1] = tf32cvt(BSA(s, c0, ks + tg + 4));
            }
            #pragma unroll
            for (int mi = 0; mi < 2; mi++)
                #pragma unroll
                for (int nj = 0; nj < NJ; nj++)
                    MMA_TF32(acc[mi][nj], af[mi], bf[nj]);
        }
    }

    // epilogue
    #pragma unroll
    for (int nj = 0; nj < NJ; nj++) {
        const int cloc = n0 + wn + (nj << 3) + (tg << 1);
        const int col  = cloc + z * zC;
        const float2 bv = *(const float2*)&bias[cloc];
        #pragma unroll
        for (int mi = 0; mi < 2; mi++) {
            const int row0 = m0 + wm + (mi << 4) + g;
            const int row1 = row0 + 8;
            float2 v0 = make_float2(acc[mi][nj][0], acc[mi][nj][1]);
            float2 v1 = make_float2(acc[mi][nj][2], acc[mi][nj][3]);
            if (EPI == 0) {
                v0.x += bv.x; v0.y += bv.y; v1.x += bv.x; v1.y += bv.y;
            } else if (EPI == 1) {
                v0.x = fmaxf(v0.x + bv.x, 0.f); v0.y = fmaxf(v0.y + bv.y, 0.f);
                v1.x = fmaxf(v1.x + bv.x, 0.f); v1.y = fmaxf(v1.y + bv.y, 0.f);
            }
            if (row0 < Mrows) {
                if (EPI == 2) {
                    const float ws = wsum[(size_t)row0 * 8 + z];
                    v0.x += ws * bv.x; v0.y += ws * bv.y;
                }
                *(float2*)&Cg[(size_t)row0 * ldc + col] = v0;
            }
            if (row1 < Mrows) {
                if (EPI == 2) {
                    const float ws = wsum[(size_t)row1 * 8 + z];
                    v1.x += ws * bv.x; v1.y += ws * bv.y;
                }
                *(float2*)&Cg[(size_t)row1 * ldc + col] = v1;
            }
        }
    }
#undef ASA
#undef BSA
}

// ---------------- deformable sampling + aggregation ----------------
__global__ __launch_bounds__(256) void sample_agg_kernel(
    const float* __restrict__ value, const float* __restrict__ ref_points)
{
    const int r    = blockIdx.x;
    const int b    = r / NQ_;
    const int m    = threadIdx.x >> 5;
    const int lane = threadIdx.x & 31;

    const float rx = ref_points[r * 2 + 0];
    const float ry = ref_points[r * 2 + 1];

    float araw = (lane < 16) ? g_qout[(size_t)r * 384 + 256 + m * 16 + lane] : -1e30f;
    float amax = araw;
    #pragma unroll
    for (int o = 8; o; o >>= 1) amax = fmaxf(amax, __shfl_xor_sync(FULLMASK, amax, o, 16));
    float e = (lane < 16) ? __expf(araw - amax) : 0.f;
    float es = e;
    #pragma unroll
    for (int o = 8; o; o >>= 1) es += __shfl_xor_sync(FULLMASK, es, o, 16);
    const float anorm = e / es;

    const float offv = g_qout[(size_t)r * 384 + m * 32 + lane];

    float a0[4] = {0.f, 0.f, 0.f, 0.f};
    float a1[4] = {0.f, 0.f, 0.f, 0.f};
    float wsum = 0.f;

    const int Hs[4]  = {92, 46, 23, 12};
    const int Wls[4] = {160, 80, 40, 20};
    const int St[4]  = {0, 14720, 18400, 19320};
    const float* vb = value + (size_t)b * S_ * C_;

#define ACCUM(ptr, wgt) do {                                          \
        const float4* _p4 = (const float4*)(ptr);                     \
        float4 _v0 = _p4[lane];                                       \
        float4 _v1 = _p4[32 + lane];                                  \
        a0[0] = fmaf(wgt, _v0.x, a0[0]);                              \
        a0[1] = fmaf(wgt, _v0.y, a0[1]);                              \
        a0[2] = fmaf(wgt, _v0.z, a0[2]);                              \
        a0[3] = fmaf(wgt, _v0.w, a0[3]);                              \
        a1[0] = fmaf(wgt, _v1.x, a1[0]);                              \
        a1[1] = fmaf(wgt, _v1.y, a1[1]);                              \
        a1[2] = fmaf(wgt, _v1.z, a1[2]);                              \
        a1[3] = fmaf(wgt, _v1.w, a1[3]);                              \
    } while (0)

    #pragma unroll
    for (int l = 0; l < 4; l++) {
        const int Hl = Hs[l], Wl = Wls[l];
        const float invW = 1.f / (float)Wl, invH = 1.f / (float)Hl;
        const float* lb = vb + (size_t)St[l] * C_;
        #pragma unroll
        for (int p = 0; p < 4; p++) {
            const int pt = l * 4 + p;
            const float a  = __shfl_sync(FULLMASK, anorm, pt);
            const float ox = __shfl_sync(FULLMASK, offv, 2 * pt);
            const float oy = __shfl_sync(FULLMASK, offv, 2 * pt + 1);
            const float x = (rx + ox * invW) * (float)Wl - 0.5f;
            const float y = (ry + oy * invH) * (float)Hl - 0.5f;
            const float xf = floorf(x), yf = floorf(y);
            const int   x0 = (int)xf,   y0 = (int)yf;
            const float lx = x - xf,    ly = y - yf;
            const float w00 = a * (1.f - lx) * (1.f - ly);
            const float w01 = a * lx * (1.f - ly);
            const float w10 = a * (1.f - lx) * ly;
            const float w11 = a * lx * ly;
            const bool vx0 = (unsigned)x0       < (unsigned)Wl;
            const bool vx1 = (unsigned)(x0 + 1) < (unsigned)Wl;
            const bool vy0 = (unsigned)y0       < (unsigned)Hl;
            const bool vy1 = (unsigned)(y0 + 1) < (unsigned)Hl;
            if (vy0) {
                const float* rp = lb + (size_t)y0 * Wl * C_;
                if (vx0) { ACCUM(rp + (size_t)x0 * C_,       w00); wsum += w00; }
                if (vx1) { ACCUM(rp + (size_t)(x0 + 1) * C_, w01); wsum += w01; }
            }
            if (vy1) {
                const float* rp = lb + (size_t)(y0 + 1) * Wl * C_;
                if (vx0) { ACCUM(rp + (size_t)x0 * C_,       w10); wsum += w10; }
                if (vx1) { ACCUM(rp + (size_t)(x0 + 1) * C_, w11); wsum += w11; }
            }
        }
    }
#undef ACCUM

    float* ag = g_agg + ((size_t)r * M_ + m) * C_;
    *(float4*)&ag[lane * 4]       = make_float4(a0[0], a0[1], a0[2], a0[3]);
    *(float4*)&ag[128 + lane * 4] = make_float4(a1[0], a1[1], a1[2], a1[3]);
    if (lane == 0) g_wsum[(size_t)r * M_ + m] = wsum;
}

// ---------------- LayerNorm helpers ----------------
__global__ __launch_bounds__(256) void ln1_kernel(
    const float* __restrict__ query,
    const float* __restrict__ lw, const float* __restrict__ lb)
{
    const int r = blockIdx.x, t = threadIdx.x;
    const size_t idx = (size_t)r * C_ + t;
    float v = query[idx] + g_feat[idx];

    __shared__ float s1[8], s2[8];
    float sum = v, sq = v * v;
    #pragma unroll
    for (int o = 16; o; o >>= 1) {
        sum += __shfl_xor_sync(FULLMASK, sum, o);
        sq  += __shfl_xor_sync(FULLMASK, sq, o);
    }
    const int lane = t & 31, wp = t >> 5;
    if (lane == 0) { s1[wp] = sum; s2[wp] = sq; }
    __syncthreads();
    float tot = 0.f, totq = 0.f;
    #pragma unroll
    for (int i = 0; i < 8; i++) { tot += s1[i]; totq += s2[i]; }
    const float mu  = tot * (1.f / 256.f);
    const float var = totq * (1.f / 256.f) - mu * mu;
    const float rs  = rsqrtf(var + 1e-6f);
    g_x1[idx] = (v - mu) * rs * lw[t] + lb[t];
}

__global__ __launch_bounds__(256) void ln2_cls_kernel(
    const float* __restrict__ lw, const float* __restrict__ lb,
    const float* __restrict__ wcls, const float* __restrict__ bcls,
    float* __restrict__ out)
{
    const int r = blockIdx.x, t = threadIdx.x;
    const size_t idx = (size_t)r * C_ + t;
    float v = g_x1[idx] + g_h2[idx];

    __shared__ float s1[8], s2[8];
    __shared__ float sred[8][10];
    float sum = v, sq = v * v;
    #pragma unroll
    for (int o = 16; o; o >>= 1) {
        sum += __shfl_xor_sync(FULLMASK, sum, o);
        sq  += __shfl_xor_sync(FULLMASK, sq, o);
    }
    const int lane = t & 31, wp = t >> 5;
    if (lane == 0) { s1[wp] = sum; s2[wp] = sq; }
    __syncthreads();
    float tot = 0.f, totq = 0.f;
    #pragma unroll
    for (int i = 0; i < 8; i++) { tot += s1[i]; totq += s2[i]; }
    const float mu  = tot * (1.f / 256.f);
    const float var = totq * (1.f / 256.f) - mu * mu;
    const float rs  = rsqrtf(var + 1e-6f);
    const float x2  = (v - mu) * rs * lw[t] + lb[t];

    float pr[10];
    #pragma unroll
    for (int j = 0; j < 10; j++) pr[j] = x2 * wcls[t * 10 + j];
    #pragma unroll
    for (int o = 16; o; o >>= 1)
        #pragma unroll
        for (int j = 0; j < 10; j++) pr[j] += __shfl_xor_sync(FULLMASK, pr[j], o);
    if (lane == 0)
        #pragma unroll
        for (int j = 0; j < 10; j++) sred[wp][j] = pr[j];
    __syncthreads();
    if (t < 10) {
        float s = bcls[t];
        #pragma unroll
        for (int i = 0; i < 8; i++) s += sred[i][t];
        out[(size_t)r * NC_ + t] = s;
    }
}

// ---------------- launch ----------------
#define SMEM64 ((4*128*20 + 4*64*20) * 4)   // 61440
#define SMEM32 ((4*128*20 + 4*32*20) * 4)   // 51200

extern "C" void kernel_launch(void* const* d_in, const int* in_sizes, int n_in,
                              void* d_out, int out_size)
{
    const float* query  = (const float*)d_in[0];
    const float* value  = (const float*)d_in[1];
    const float* refp   = (const float*)d_in[2];
    const float* w_value= (const float*)d_in[3];
    const float* b_value= (const float*)d_in[4];
    const float* w_off  = (const float*)d_in[5];
    const float* b_off  = (const float*)d_in[6];
    const float* w_attn = (const float*)d_in[7];
    const float* b_attn = (const float*)d_in[8];
    const float* w_out  = (const float*)d_in[9];
    const float* b_out  = (const float*)d_in[10];
    const float* ln1w   = (const float*)d_in[11];
    const float* ln1b   = (const float*)d_in[12];
    const float* w_ffn1 = (const float*)d_in[13];
    const float* b_ffn1 = (const float*)d_in[14];
    const float* w_ffn2 = (const float*)d_in[15];
    const float* b_ffn2 = (const float*)d_in[16];
    const float* ln2w   = (const float*)d_in[17];
    const float* ln2b   = (const float*)d_in[18];
    const float* w_cls  = (const float*)d_in[19];
    const float* b_cls  = (const float*)d_in[20];
    float* out = (float*)d_out;

    float *p_qout, *p_agg, *p_wsum, *p_featv, *p_feat, *p_x1, *p_h, *p_h2;
    float *p_wqT, *p_bq, *p_woutT, *p_f1T, *p_f2T, *p_wvT;
    cudaGetSymbolAddress((void**)&p_qout,  g_qout);
    cudaGetSymbolAddress((void**)&p_agg,   g_agg);
    cudaGetSymbolAddress((void**)&p_wsum,  g_wsum);
    cudaGetSymbolAddress((void**)&p_featv, g_featv);
    cudaGetSymbolAddress((void**)&p_feat,  g_feat);
    cudaGetSymbolAddress((void**)&p_x1,    g_x1);
    cudaGetSymbolAddress((void**)&p_h,     g_h);
    cudaGetSymbolAddress((void**)&p_h2,    g_h2);
    cudaGetSymbolAddress((void**)&p_wqT,   g_wqT);
    cudaGetSymbolAddress((void**)&p_bq,    g_bq);
    cudaGetSymbolAddress((void**)&p_woutT, g_woutT);
    cudaGetSymbolAddress((void**)&p_f1T,   g_f1T);
    cudaGetSymbolAddress((void**)&p_f2T,   g_f2T);
    cudaGetSymbolAddress((void**)&p_wvT,   g_wvT);

    cudaFuncSetAttribute(gemm_cp<64,0>, cudaFuncAttributeMaxDynamicSharedMemorySize, SMEM64);
    cudaFuncSetAttribute(gemm_cp<64,1>, cudaFuncAttributeMaxDynamicSharedMemorySize, SMEM64);
    cudaFuncSetAttribute(gemm_cp<32,2>, cudaFuncAttributeMaxDynamicSharedMemorySize, SMEM32);

    // 0. weight prep
    prep_weights<<<2944, 256>>>(w_off, w_attn, b_off, b_attn, w_out, w_ffn1, w_ffn2, w_value);
    // 1. fused query projection: [off | attn] = query @ [w_off | w_attn]
    gemm_cp<64,0><<<dim3(MT_, 6), 256, SMEM64>>>(query, C_, 0, p_wqT, 256, 0, p_bq, 0,
                                                 nullptr, p_qout, 384, 0, R_, 256);
    // 2. deformable sampling + weighted aggregation of raw value rows
    sample_agg_kernel<<<R_, 256>>>(value, refp);
    // 3. per-head value projection (thin GEMM N=32 per head, grid z = 8)
    gemm_cp<32,2><<<dim3(MT_, 1, M_), 256, SMEM32>>>(p_agg, 2048, 256, p_wvT, 256, 8192,
                                                     b_value, 32, p_wsum, p_featv, C_, 32, R_, 256);
    // 4. output projection
    gemm_cp<64,0><<<dim3(MT_, 4), 256, SMEM64>>>(p_featv, C_, 0, p_woutT, 256, 0, b_out, 0,
                                                 nullptr, p_feat, C_, 0, R_, 256);
    // 5. residual + LN1
    ln1_kernel<<<R_, 256>>>(query, ln1w, ln1b);
    // 6. FFN
    gemm_cp<64,1><<<dim3(MT_, 16), 256, SMEM64>>>(p_x1, C_, 0, p_f1T, 256, 0, b_ffn1, 0,
                                                  nullptr, p_h, FFN_, 0, R_, 256);
    gemm_cp<64,0><<<dim3(MT_, 4), 256, SMEM64>>>(p_h, FFN_, 0, p_f2T, 1024, 0, b_ffn2, 0,
                                                 nullptr, p_h2, C_, 0, R_, 1024);
    // 7. residual + LN2 + classifier
    ln2_cls_kernel<<<R_, 256>>>(ln2w, ln2b, w_cls, b_cls, out);
}

// round 6
// speedup vs baseline: 1.9417x; 1.3361x over previous
#include <cuda_runtime.h>
#include <cuda_bf16.h>
#include <math.h>
#include <stdint.h>

#define FULLMASK 0xffffffffu

// Problem constants
#define B_    8
#define NQ_   900
#define C_    256
#define M_    8
#define D_    32
#define S_    19560
#define FFN_  1024
#define NC_   10
#define R_    (B_*NQ_)            // 7200 rows
#define MT_   ((R_ + 127) / 128)  // 57 M tiles

typedef __nv_bfloat16  bf16;
typedef __nv_bfloat162 bf162;

// ---------------- scratch (static device globals) ----------------
__device__ float g_qout [R_ * 384];        // [off(256) | attn(128)] per row (fp32)
__device__ bf16  g_aggh [R_ * M_ * C_];    // aggregated value rows, bf16
__device__ float g_wsum [R_ * M_];
__device__ bf16  g_featvh[R_ * C_];        // per-head projected features, bf16
__device__ float g_feat [R_ * C_];         // after w_out (fp32, LN input)
__device__ float g_x1   [R_ * C_];         // after LN1 (fp32, residual)
__device__ bf16  g_x1h  [R_ * C_];         // after LN1 (bf16, ffn1 input)
__device__ bf16  g_hh   [R_ * FFN_];       // FFN hidden, bf16
__device__ float g_h2   [R_ * C_];         // after w_ffn2 (fp32)
// bf16 weights [N, K] + bf16 query
__device__ bf16  g_qbf  [R_ * C_];
__device__ bf16  g_wqTh [384 * 256];
__device__ float g_bq   [384];
__device__ bf16  g_woutTh[256 * 256];
__device__ bf16  g_f1Th [1024 * 256];
__device__ bf16  g_f2Th [256 * 1024];
__device__ bf16  g_wvTh [M_ * D_ * 256];   // per-head value-proj slice [8][32][256]

// bf16 m16n8k16 warp MMA
#define MMA_BF16(c, a, b) \
    asm volatile("mma.sync.aligned.m16n8k16.row.col.f32.bf16.bf16.f32 " \
        "{%0,%1,%2,%3}, {%4,%5,%6,%7}, {%8,%9}, {%0,%1,%2,%3};" \
        : "+f"((c)[0]), "+f"((c)[1]), "+f"((c)[2]), "+f"((c)[3]) \
        : "r"((a)[0]), "r"((a)[1]), "r"((a)[2]), "r"((a)[3]), \
          "r"((b)[0]), "r"((b)[1]))

#define CP_ASYNC16(saddr, gaddr, srcsz) \
    asm volatile("cp.async.cg.shared.global [%0], [%1], 16, %2;" \
        :: "r"(saddr), "l"(gaddr), "r"(srcsz))
#define CP_COMMIT()  asm volatile("cp.async.commit_group;" ::: "memory")
#define CP_WAIT2()   asm volatile("cp.async.wait_group 2;" ::: "memory")

// ---------------- weight / activation prep (all bf16 conversions) ----------------
__global__ __launch_bounds__(256) void prep_weights(
    const float* __restrict__ query,
    const float* __restrict__ w_off, const float* __restrict__ w_attn,
    const float* __restrict__ b_off, const float* __restrict__ b_attn,
    const float* __restrict__ w_out_, const float* __restrict__ w_ffn1,
    const float* __restrict__ w_ffn2, const float* __restrict__ w_value)
{
    int idx = blockIdx.x * 256 + threadIdx.x;
    if (idx < 98304) {                                   // wqTh [384,256]
        int n = idx >> 8, k = idx & 255;
        g_wqTh[idx] = __float2bfloat16_rn((n < 256) ? w_off[k * 256 + n]
                                                    : w_attn[k * 128 + (n - 256)]);
        if (idx < 384) g_bq[idx] = (idx < 256) ? b_off[idx] : b_attn[idx - 256];
        return;
    }
    idx -= 98304;
    if (idx < 65536) {                                   // woutTh [256,256]
        int n = idx >> 8, k = idx & 255;
        g_woutTh[idx] = __float2bfloat16_rn(w_out_[k * 256 + n]);
        return;
    }
    idx -= 65536;
    if (idx < 262144) {                                  // f1Th [1024,256]
        int n = idx >> 8, k = idx & 255;
        g_f1Th[idx] = __float2bfloat16_rn(w_ffn1[k * 1024 + n]);
        return;
    }
    idx -= 262144;
    if (idx < 262144) {                                  // f2Th [256,1024]
        int n = idx >> 10, k = idx & 1023;
        g_f2Th[idx] = __float2bfloat16_rn(w_ffn2[k * 256 + n]);
        return;
    }
    idx -= 262144;
    if (idx < 65536) {                                   // wvTh [8][32][256]
        int m = idx >> 13, n = (idx >> 8) & 31, k = idx & 255;
        g_wvTh[idx] = __float2bfloat16_rn(w_value[k * 256 + m * 32 + n]);
        return;
    }
    idx -= 65536;
    if (idx < R_ * C_ / 4) {                             // qbf (float4 -> 4 bf16)
        float4 v = *(const float4*)&query[idx * 4];
        bf162 p0 = __floats2bfloat162_rn(v.x, v.y);
        bf162 p1 = __floats2bfloat162_rn(v.z, v.w);
        uint2 u;
        u.x = *(uint32_t*)&p0; u.y = *(uint32_t*)&p1;
        *(uint2*)&g_qbf[idx * 4] = u;
        return;
    }
}

// ---------------- bf16 mma GEMM w/ cp.async 4-stage pipeline ----------------
// BM=128, 8 warps as 4(M) x 2(N); warp tile 32 x BN/2. K per stage = 32.
// EPI: 0 = +bias, 1 = relu(+bias), 2 = +wsum[row, z]*bias
// OBF: 1 = store bf16 output, 0 = fp32
template<int BN, int EPI, int OBF>
__global__ __launch_bounds__(256) void gemm_bf(
    const bf16* __restrict__ A, int lda, int zA,
    const bf16* __restrict__ WT, int ldb, int zB,
    const float* __restrict__ bias, int zbias,
    const float* __restrict__ wsum,
    void* __restrict__ Cg, int ldc, int zC,
    int Mrows, int Klen)
{
    constexpr int WN = BN / 2;
    constexpr int NJ = WN / 8;
    extern __shared__ float smp[];
    float* As = smp;                    // [4][128][20] (each float = bf16 pair)
    float* Bs = smp + 4 * 128 * 20;     // [4][BN][20]
#define ASA(s,r,c) As[(((s) << 7) + (r)) * 20 + (c)]
#define BSA(s,r,c) Bs[((s) * BN + (r)) * 20 + (c)]

    const int tid  = threadIdx.x;
    const int wid  = tid >> 5, lane = tid & 31;
    const int g    = lane >> 2, tg = lane & 3;
    const int wm   = (wid & 3) << 5;      // 0,32,64,96
    const int wn   = (wid >> 2) * WN;     // 0 or WN
    const int m0   = blockIdx.x * 128;
    const int n0   = blockIdx.y * BN;
    const int z    = blockIdx.z;

    A    += (size_t)z * zA;
    WT   += (size_t)z * zB;
    bias += z * zbias;

    // load mapping: A row = 32 bf16 = 64B -> 2 threads/row, 2x16B each
    const int ar  = tid >> 1;                 // A row 0..127
    const int aw  = (tid & 1) << 3;           // A word offset 0 or 8 (u32 words)
    const int br  = tid >> 2;                 // B row
    const int bw  = (tid & 3) << 2;           // B word offset 0,4,8,12
    const uint32_t aval = ((m0 + ar) < Mrows) ? 16u : 0u;
    const bool bldr = (BN == 64) || (tid < 128);
    const bf16* agp = A  + (size_t)(m0 + ar) * lda + (aw << 1);   // elements
    const bf16* bgp = WT + (size_t)(n0 + br) * ldb + (bw << 1);

    const int niter = Klen >> 5;   // K=32 per stage

    auto issue = [&](int kb, int s) {
        uint32_t sa = (uint32_t)__cvta_generic_to_shared(&ASA(s, ar, aw));
        CP_ASYNC16(sa,      agp + (kb << 5),     aval);
        CP_ASYNC16(sa + 16, agp + (kb << 5) + 8, aval);
        if (bldr) {
            uint32_t sb = (uint32_t)__cvta_generic_to_shared(&BSA(s, br, bw));
            CP_ASYNC16(sb, bgp + (kb << 5), 16u);
        }
    };

    float acc[2][NJ][4];
    #pragma unroll
    for (int i = 0; i < 2; i++)
        #pragma unroll
        for (int j = 0; j < NJ; j++)
            #pragma unroll
            for (int v = 0; v < 4; v++) acc[i][j][v] = 0.f;

    issue(0, 0); CP_COMMIT();
    issue(1, 1); CP_COMMIT();
    issue(2, 2); CP_COMMIT();

    for (int it = 0; it < niter; it++) {
        const int s = it & 3;
        CP_WAIT2();
        __syncthreads();
        if (it + 3 < niter) issue(it + 3, (it + 3) & 3);
        CP_COMMIT();

        #pragma unroll
        for (int ks = 0; ks < 16; ks += 8) {   // 2 mma-k16 steps per stage
            uint32_t af[2][4], bf[NJ][2];
            #pragma unroll
            for (int mi = 0; mi < 2; mi++) {
                const int r0 = wm + (mi << 4) + g;
                af[mi][0] = __float_as_uint(ASA(s, r0,     ks + tg));
                af[mi][1] = __float_as_uint(ASA(s, r0 + 8, ks + tg));
                af[mi][2] = __float_as_uint(ASA(s, r0,     ks + tg + 4));
                af[mi][3] = __float_as_uint(ASA(s, r0 + 8, ks + tg + 4));
            }
            #pragma unroll
            for (int nj = 0; nj < NJ; nj++) {
                const int c0 = wn + (nj << 3) + g;
                bf[nj][0] = __float_as_uint(BSA(s, c0, ks + tg));
                bf[nj][1] = __float_as_uint(BSA(s, c0, ks + tg + 4));
            }
            #pragma unroll
            for (int mi = 0; mi < 2; mi++)
                #pragma unroll
                for (int nj = 0; nj < NJ; nj++)
                    MMA_BF16(acc[mi][nj], af[mi], bf[nj]);
        }
    }

    // epilogue
    #pragma unroll
    for (int nj = 0; nj < NJ; nj++) {
        const int cloc = n0 + wn + (nj << 3) + (tg << 1);
        const int col  = cloc + z * zC;
        const float2 bv = *(const float2*)&bias[cloc];
        #pragma unroll
        for (int mi = 0; mi < 2; mi++) {
            const int row0 = m0 + wm + (mi << 4) + g;
            const int row1 = row0 + 8;
            float2 v0 = make_float2(acc[mi][nj][0], acc[mi][nj][1]);
            float2 v1 = make_float2(acc[mi][nj][2], acc[mi][nj][3]);
            if (EPI == 0) {
                v0.x += bv.x; v0.y += bv.y; v1.x += bv.x; v1.y += bv.y;
            } else if (EPI == 1) {
                v0.x = fmaxf(v0.x + bv.x, 0.f); v0.y = fmaxf(v0.y + bv.y, 0.f);
                v1.x = fmaxf(v1.x + bv.x, 0.f); v1.y = fmaxf(v1.y + bv.y, 0.f);
            }
            if (row0 < Mrows) {
                if (EPI == 2) {
                    const float ws = wsum[(size_t)row0 * 8 + z];
                    v0.x += ws * bv.x; v0.y += ws * bv.y;
                }
                if (OBF) {
                    bf162 p = __floats2bfloat162_rn(v0.x, v0.y);
                    *(bf162*)((bf16*)Cg + (size_t)row0 * ldc + col) = p;
                } else {
                    *(float2*)((float*)Cg + (size_t)row0 * ldc + col) = v0;
                }
            }
            if (row1 < Mrows) {
                if (EPI == 2) {
                    const float ws = wsum[(size_t)row1 * 8 + z];
                    v1.x += ws * bv.x; v1.y += ws * bv.y;
                }
                if (OBF) {
                    bf162 p = __floats2bfloat162_rn(v1.x, v1.y);
                    *(bf162*)((bf16*)Cg + (size_t)row1 * ldc + col) = p;
                } else {
                    *(float2*)((float*)Cg + (size_t)row1 * ldc + col) = v1;
                }
            }
        }
    }
#undef ASA
#undef BSA
}

// ---------------- deformable sampling + aggregation (bf16 output) ----------------
__global__ __launch_bounds__(256) void sample_agg_kernel(
    const float* __restrict__ value, const float* __restrict__ ref_points)
{
    const int r    = blockIdx.x;
    const int b    = r / NQ_;
    const int m    = threadIdx.x >> 5;
    const int lane = threadIdx.x & 31;

    const float rx = ref_points[r * 2 + 0];
    const float ry = ref_points[r * 2 + 1];

    float araw = (lane < 16) ? g_qout[(size_t)r * 384 + 256 + m * 16 + lane] : -1e30f;
    float amax = araw;
    #pragma unroll
    for (int o = 8; o; o >>= 1) amax = fmaxf(amax, __shfl_xor_sync(FULLMASK, amax, o, 16));
    float e = (lane < 16) ? __expf(araw - amax) : 0.f;
    float es = e;
    #pragma unroll
    for (int o = 8; o; o >>= 1) es += __shfl_xor_sync(FULLMASK, es, o, 16);
    const float anorm = e / es;

    const float offv = g_qout[(size_t)r * 384 + m * 32 + lane];

    float a0[4] = {0.f, 0.f, 0.f, 0.f};
    float a1[4] = {0.f, 0.f, 0.f, 0.f};
    float wsum = 0.f;

    const int Hs[4]  = {92, 46, 23, 12};
    const int Wls[4] = {160, 80, 40, 20};
    const int St[4]  = {0, 14720, 18400, 19320};
    const float* vb = value + (size_t)b * S_ * C_;

#define ACCUM(ptr, wgt) do {                                          \
        const float4* _p4 = (const float4*)(ptr);                     \
        float4 _v0 = _p4[lane];                                       \
        float4 _v1 = _p4[32 + lane];                                  \
        a0[0] = fmaf(wgt, _v0.x, a0[0]);                              \
        a0[1] = fmaf(wgt, _v0.y, a0[1]);                              \
        a0[2] = fmaf(wgt, _v0.z, a0[2]);                              \
        a0[3] = fmaf(wgt, _v0.w, a0[3]);                              \
        a1[0] = fmaf(wgt, _v1.x, a1[0]);                              \
        a1[1] = fmaf(wgt, _v1.y, a1[1]);                              \
        a1[2] = fmaf(wgt, _v1.z, a1[2]);                              \
        a1[3] = fmaf(wgt, _v1.w, a1[3]);                              \
    } while (0)

    #pragma unroll
    for (int l = 0; l < 4; l++) {
        const int Hl = Hs[l], Wl = Wls[l];
        const float invW = 1.f / (float)Wl, invH = 1.f / (float)Hl;
        const float* lb = vb + (size_t)St[l] * C_;
        #pragma unroll
        for (int p = 0; p < 4; p++) {
            const int pt = l * 4 + p;
            const float a  = __shfl_sync(FULLMASK, anorm, pt);
            const float ox = __shfl_sync(FULLMASK, offv, 2 * pt);
            const float oy = __shfl_sync(FULLMASK, offv, 2 * pt + 1);
            const float x = (rx + ox * invW) * (float)Wl - 0.5f;
            const float y = (ry + oy * invH) * (float)Hl - 0.5f;
            const float xf = floorf(x), yf = floorf(y);
            const int   x0 = (int)xf,   y0 = (int)yf;
            const float lx = x - xf,    ly = y - yf;
            const float w00 = a * (1.f - lx) * (1.f - ly);
            const float w01 = a * lx * (1.f - ly);
            const float w10 = a * (1.f - lx) * ly;
            const float w11 = a * lx * ly;
            const bool vx0 = (unsigned)x0       < (unsigned)Wl;
            const bool vx1 = (unsigned)(x0 + 1) < (unsigned)Wl;
            const bool vy0 = (unsigned)y0       < (unsigned)Hl;
            const bool vy1 = (unsigned)(y0 + 1) < (unsigned)Hl;
            if (vy0) {
                const float* rp = lb + (size_t)y0 * Wl * C_;
                if (vx0) { ACCUM(rp + (size_t)x0 * C_,       w00); wsum += w00; }
                if (vx1) { ACCUM(rp + (size_t)(x0 + 1) * C_, w01); wsum += w01; }
            }
            if (vy1) {
                const float* rp = lb + (size_t)(y0 + 1) * Wl * C_;
                if (vx0) { ACCUM(rp + (size_t)x0 * C_,       w10); wsum += w10; }
                if (vx1) { ACCUM(rp + (size_t)(x0 + 1) * C_, w11); wsum += w11; }
            }
        }
    }
#undef ACCUM

    bf16* ag = g_aggh + ((size_t)r * M_ + m) * C_;
    {
        bf162 p0 = __floats2bfloat162_rn(a0[0], a0[1]);
        bf162 p1 = __floats2bfloat162_rn(a0[2], a0[3]);
        uint2 u; u.x = *(uint32_t*)&p0; u.y = *(uint32_t*)&p1;
        *(uint2*)(ag + lane * 4) = u;
        p0 = __floats2bfloat162_rn(a1[0], a1[1]);
        p1 = __floats2bfloat162_rn(a1[2], a1[3]);
        u.x = *(uint32_t*)&p0; u.y = *(uint32_t*)&p1;
        *(uint2*)(ag + 128 + lane * 4) = u;
    }
    if (lane == 0) g_wsum[(size_t)r * M_ + m] = wsum;
}

// ---------------- LayerNorm helpers ----------------
__global__ __launch_bounds__(256) void ln1_kernel(
    const float* __restrict__ query,
    const float* __restrict__ lw, const float* __restrict__ lb)
{
    const int r = blockIdx.x, t = threadIdx.x;
    const size_t idx = (size_t)r * C_ + t;
    float v = query[idx] + g_feat[idx];

    __shared__ float s1[8], s2[8];
    float sum = v, sq = v * v;
    #pragma unroll
    for (int o = 16; o; o >>= 1) {
        sum += __shfl_xor_sync(FULLMASK, sum, o);
        sq  += __shfl_xor_sync(FULLMASK, sq, o);
    }
    const int lane = t & 31, wp = t >> 5;
    if (lane == 0) { s1[wp] = sum; s2[wp] = sq; }
    __syncthreads();
    float tot = 0.f, totq = 0.f;
    #pragma unroll
    for (int i = 0; i < 8; i++) { tot += s1[i]; totq += s2[i]; }
    const float mu  = tot * (1.f / 256.f);
    const float var = totq * (1.f / 256.f) - mu * mu;
    const float rs  = rsqrtf(var + 1e-6f);
    const float o   = (v - mu) * rs * lw[t] + lb[t];
    g_x1[idx]  = o;
    g_x1h[idx] = __float2bfloat16_rn(o);
}

__global__ __launch_bounds__(256) void ln2_cls_kernel(
    const float* __restrict__ lw, const float* __restrict__ lb,
    const float* __restrict__ wcls, const float* __restrict__ bcls,
    float* __restrict__ out)
{
    const int r = blockIdx.x, t = threadIdx.x;
    const size_t idx = (size_t)r * C_ + t;
    float v = g_x1[idx] + g_h2[idx];

    __shared__ float s1[8], s2[8];
    __shared__ float sred[8][10];
    float sum = v, sq = v * v;
    #pragma unroll
    for (int o = 16; o; o >>= 1) {
        sum += __shfl_xor_sync(FULLMASK, sum, o);
        sq  += __shfl_xor_sync(FULLMASK, sq, o);
    }
    const int lane = t & 31, wp = t >> 5;
    if (lane == 0) { s1[wp] = sum; s2[wp] = sq; }
    __syncthreads();
    float tot = 0.f, totq = 0.f;
    #pragma unroll
    for (int i = 0; i < 8; i++) { tot += s1[i]; totq += s2[i]; }
    const float mu  = tot * (1.f / 256.f);
    const float var = totq * (1.f / 256.f) - mu * mu;
    const float rs  = rsqrtf(var + 1e-6f);
    const float x2  = (v - mu) * rs * lw[t] + lb[t];

    float pr[10];
    #pragma unroll
    for (int j = 0; j < 10; j++) pr[j] = x2 * wcls[t * 10 + j];
    #pragma unroll
    for (int o = 16; o; o >>= 1)
        #pragma unroll
        for (int j = 0; j < 10; j++) pr[j] += __shfl_xor_sync(FULLMASK, pr[j], o);
    if (lane == 0)
        #pragma unroll
        for (int j = 0; j < 10; j++) sred[wp][j] = pr[j];
    __syncthreads();
    if (t < 10) {
        float s = bcls[t];
        #pragma unroll
        for (int i = 0; i < 8; i++) s += sred[i][t];
        out[(size_t)r * NC_ + t] = s;
    }
}

// ---------------- launch ----------------
#define SMEM64 ((4*128*20 + 4*64*20) * 4)   // 61440
#define SMEM32 ((4*128*20 + 4*32*20) * 4)   // 51200

extern "C" void kernel_launch(void* const* d_in, const int* in_sizes, int n_in,
                              void* d_out, int out_size)
{
    const float* query  = (const float*)d_in[0];
    const float* value  = (const float*)d_in[1];
    const float* refp   = (const float*)d_in[2];
    const float* w_value= (const float*)d_in[3];
    const float* b_value= (const float*)d_in[4];
    const float* w_off  = (const float*)d_in[5];
    const float* b_off  = (const float*)d_in[6];
    const float* w_attn = (const float*)d_in[7];
    const float* b_attn = (const float*)d_in[8];
    const float* w_out  = (const float*)d_in[9];
    const float* b_out  = (const float*)d_in[10];
    const float* ln1w   = (const float*)d_in[11];
    const float* ln1b   = (const float*)d_in[12];
    const float* w_ffn1 = (const float*)d_in[13];
    const float* b_ffn1 = (const float*)d_in[14];
    const float* w_ffn2 = (const float*)d_in[15];
    const float* b_ffn2 = (const float*)d_in[16];
    const float* ln2w   = (const float*)d_in[17];
    const float* ln2b   = (const float*)d_in[18];
    const float* w_cls  = (const float*)d_in[19];
    const float* b_cls  = (const float*)d_in[20];
    float* out = (float*)d_out;

    float *p_qout, *p_wsum, *p_feat, *p_x1, *p_h2, *p_bq;
    bf16  *p_aggh, *p_featvh, *p_x1h, *p_hh, *p_qbf;
    bf16  *p_wqTh, *p_woutTh, *p_f1Th, *p_f2Th, *p_wvTh;
    cudaGetSymbolAddress((void**)&p_qout,   g_qout);
    cudaGetSymbolAddress((void**)&p_aggh,   g_aggh);
    cudaGetSymbolAddress((void**)&p_wsum,   g_wsum);
    cudaGetSymbolAddress((void**)&p_featvh, g_featvh);
    cudaGetSymbolAddress((void**)&p_feat,   g_feat);
    cudaGetSymbolAddress((void**)&p_x1,     g_x1);
    cudaGetSymbolAddress((void**)&p_x1h,    g_x1h);
    cudaGetSymbolAddress((void**)&p_hh,     g_hh);
    cudaGetSymbolAddress((void**)&p_h2,     g_h2);
    cudaGetSymbolAddress((void**)&p_qbf,    g_qbf);
    cudaGetSymbolAddress((void**)&p_wqTh,   g_wqTh);
    cudaGetSymbolAddress((void**)&p_bq,     g_bq);
    cudaGetSymbolAddress((void**)&p_woutTh, g_woutTh);
    cudaGetSymbolAddress((void**)&p_f1Th,   g_f1Th);
    cudaGetSymbolAddress((void**)&p_f2Th,   g_f2Th);
    cudaGetSymbolAddress((void**)&p_wvTh,   g_wvTh);

    cudaFuncSetAttribute(gemm_bf<64,0,0>, cudaFuncAttributeMaxDynamicSharedMemorySize, SMEM64);
    cudaFuncSetAttribute(gemm_bf<64,1,1>, cudaFuncAttributeMaxDynamicSharedMemorySize, SMEM64);
    cudaFuncSetAttribute(gemm_bf<32,2,1>, cudaFuncAttributeMaxDynamicSharedMemorySize, SMEM32);

    // 0. weight + query bf16 prep
    prep_weights<<<9990, 256>>>(query, w_off, w_attn, b_off, b_attn,
                                w_out, w_ffn1, w_ffn2, w_value);
    // 1. fused query projection: [off | attn] = q @ [w_off | w_attn]
    gemm_bf<64,0,0><<<dim3(MT_, 6), 256, SMEM64>>>(p_qbf, C_, 0, p_wqTh, 256, 0, p_bq, 0,
                                                   nullptr, p_qout, 384, 0, R_, 256);
    // 2. deformable sampling + weighted aggregation (bf16 agg out)
    sample_agg_kernel<<<R_, 256>>>(value, refp);
    // 3. per-head value projection (thin GEMM N=32 per head, z = 8)
    gemm_bf<32,2,1><<<dim3(MT_, 1, M_), 256, SMEM32>>>(p_aggh, 2048, 256, p_wvTh, 256, 8192,
                                                       b_value, 32, p_wsum,
                                                       p_featvh, C_, 32, R_, 256);
    // 4. output projection (fp32 out for LN)
    gemm_bf<64,0,0><<<dim3(MT_, 4), 256, SMEM64>>>(p_featvh, C_, 0, p_woutTh, 256, 0, b_out, 0,
                                                   nullptr, p_feat, C_, 0, R_, 256);
    // 5. residual + LN1 (fp32 + bf16 mirror)
    ln1_kernel<<<R_, 256>>>(query, ln1w, ln1b);
    // 6. FFN
    gemm_bf<64,1,1><<<dim3(MT_, 16), 256, SMEM64>>>(p_x1h, C_, 0, p_f1Th, 256, 0, b_ffn1, 0,
                                                    nullptr, p_hh, FFN_, 0, R_, 256);
    gemm_bf<64,0,0><<<dim3(MT_, 4), 256, SMEM64>>>(p_hh, FFN_, 0, p_f2Th, 1024, 0, b_ffn2, 0,
                                                   nullptr, p_h2, C_, 0, R_, 1024);
    // 7. residual + LN2 + classifier
    ln2_cls_kernel<<<R_, 256>>>(ln2w, ln2b, w_cls, b_cls, out);
}

// round 7
// speedup vs baseline: 2.0432x; 1.0523x over previous
#include <cuda_runtime.h>
#include <cuda_bf16.h>
#include <math.h>
#include <stdint.h>

#define FULLMASK 0xffffffffu

// Problem constants
#define B_    8
#define NQ_   900
#define C_    256
#define M_    8
#define D_    32
#define S_    19560
#define FFN_  1024
#define NC_   10
#define R_    (B_*NQ_)            // 7200 rows
#define MT_   ((R_ + 127) / 128)  // 57 M tiles

typedef __nv_bfloat16  bf16;
typedef __nv_bfloat162 bf162;

// ---------------- scratch (static device globals) ----------------
__device__ float g_qout [R_ * 384];        // [off(256) | attn(128)] per row (fp32)
__device__ bf16  g_aggh [R_ * M_ * C_];    // aggregated value rows, bf16
__device__ float g_wsum [R_ * M_];
__device__ bf16  g_featvh[R_ * C_];        // per-head projected features, bf16
__device__ float g_feat [R_ * C_];         // after w_out (fp32, LN input)
__device__ float g_x1   [R_ * C_];         // after LN1 (fp32, residual)
__device__ bf16  g_x1h  [R_ * C_];         // after LN1 (bf16, ffn1 input)
__device__ bf16  g_hh   [R_ * FFN_];       // FFN hidden, bf16
__device__ float g_h2   [R_ * C_];         // after w_ffn2 (fp32)
// bf16 weights [N, K] + bf16 query
__device__ bf16  g_qbf  [R_ * C_];
__device__ bf16  g_wqTh [384 * 256];
__device__ float g_bq   [384];
__device__ bf16  g_woutTh[256 * 256];
__device__ bf16  g_f1Th [1024 * 256];
__device__ bf16  g_f2Th [256 * 1024];
__device__ bf16  g_wvTh [M_ * D_ * 256];   // per-head value-proj slice [8][32][256]

// bf16 m16n8k16 warp MMA
#define MMA_BF16(c, a, b) \
    asm volatile("mma.sync.aligned.m16n8k16.row.col.f32.bf16.bf16.f32 " \
        "{%0,%1,%2,%3}, {%4,%5,%6,%7}, {%8,%9}, {%0,%1,%2,%3};" \
        : "+f"((c)[0]), "+f"((c)[1]), "+f"((c)[2]), "+f"((c)[3]) \
        : "r"((a)[0]), "r"((a)[1]), "r"((a)[2]), "r"((a)[3]), \
          "r"((b)[0]), "r"((b)[1]))

__device__ __forceinline__ void ldsm_x4(uint32_t& r0, uint32_t& r1, uint32_t& r2,
                                        uint32_t& r3, const void* p) {
    uint32_t a = (uint32_t)__cvta_generic_to_shared(p);
    asm volatile("ldmatrix.sync.aligned.m8n8.x4.shared.b16 {%0,%1,%2,%3}, [%4];"
                 : "=r"(r0), "=r"(r1), "=r"(r2), "=r"(r3) : "r"(a));
}

#define CP_ASYNC16(saddr, gaddr, srcsz) \
    asm volatile("cp.async.cg.shared.global [%0], [%1], 16, %2;" \
        :: "r"(saddr), "l"(gaddr), "r"(srcsz))
#define CP_COMMIT()  asm volatile("cp.async.commit_group;" ::: "memory")
#define CP_WAIT1()   asm volatile("cp.async.wait_group 1;" ::: "memory")

// ---------------- weight / activation prep (all bf16 conversions) ----------------
__global__ __launch_bounds__(256) void prep_weights(
    const float* __restrict__ query,
    const float* __restrict__ w_off, const float* __restrict__ w_attn,
    const float* __restrict__ b_off, const float* __restrict__ b_attn,
    const float* __restrict__ w_out_, const float* __restrict__ w_ffn1,
    const float* __restrict__ w_ffn2, const float* __restrict__ w_value)
{
    int idx = blockIdx.x * 256 + threadIdx.x;
    if (idx < 98304) {                                   // wqTh [384,256]
        int n = idx >> 8, k = idx & 255;
        g_wqTh[idx] = __float2bfloat16_rn((n < 256) ? w_off[k * 256 + n]
                                                    : w_attn[k * 128 + (n - 256)]);
        if (idx < 384) g_bq[idx] = (idx < 256) ? b_off[idx] : b_attn[idx - 256];
        return;
    }
    idx -= 98304;
    if (idx < 65536) {                                   // woutTh [256,256]
        int n = idx >> 8, k = idx & 255;
        g_woutTh[idx] = __float2bfloat16_rn(w_out_[k * 256 + n]);
        return;
    }
    idx -= 65536;
    if (idx < 262144) {                                  // f1Th [1024,256]
        int n = idx >> 8, k = idx & 255;
        g_f1Th[idx] = __float2bfloat16_rn(w_ffn1[k * 1024 + n]);
        return;
    }
    idx -= 262144;
    if (idx < 262144) {                                  // f2Th [256,1024]
        int n = idx >> 10, k = idx & 1023;
        g_f2Th[idx] = __float2bfloat16_rn(w_ffn2[k * 256 + n]);
        return;
    }
    idx -= 262144;
    if (idx < 65536) {                                   // wvTh [8][32][256]
        int m = idx >> 13, n = (idx >> 8) & 31, k = idx & 255;
        g_wvTh[idx] = __float2bfloat16_rn(w_value[k * 256 + m * 32 + n]);
        return;
    }
    idx -= 65536;
    if (idx < R_ * C_ / 4) {                             // qbf (float4 -> 4 bf16)
        float4 v = *(const float4*)&query[idx * 4];
        bf162 p0 = __floats2bfloat162_rn(v.x, v.y);
        bf162 p1 = __floats2bfloat162_rn(v.z, v.w);
        uint2 u;
        u.x = *(uint32_t*)&p0; u.y = *(uint32_t*)&p1;
        *(uint2*)&g_qbf[idx * 4] = u;
        return;
    }
}

// ---------------- bf16 mma GEMM: ldmatrix + 3-stage cp.async pipeline ----------------
// BM=128, 8 warps as 4(M) x 2(N); warp tile 32 x BN/2. K per stage = 32.
// EPI: 0 = +bias, 1 = relu(+bias), 2 = +wsum[row, z]*bias
// OBF: 1 = store bf16 output, 0 = fp32
template<int BN, int EPI, int OBF>
__global__ __launch_bounds__(256) void gemm_bf(
    const bf16* __restrict__ A, int lda, int zA,
    const bf16* __restrict__ WT, int ldb, int zB,
    const float* __restrict__ bias, int zbias,
    const float* __restrict__ wsum,
    void* __restrict__ Cg, int ldc, int zC,
    int Mrows, int Klen)
{
    constexpr int WN = BN / 2;
    constexpr int NJ = WN / 8;       // 2 for BN=32, 4 for BN=64? no: WN/8 -> BN=64: 4? (WN=32 -> 4)
    // NOTE: WN=BN/2; NJ = WN/8: BN=64 -> WN=32 -> NJ=4? careful: previous rounds used NJ=WN/8=4 for BN=64?
    // Prior working code: BN=64 -> WN=32, NJ=WN/8=4? It used NJ=2? Recheck: NJ = WN/8 = 32/8 = 4.
    // Prior rounds had "NJ = WN / 8" with BN=64 -> NJ=4? They declared acc[2][NJ][4]; loops nj<NJ with col
    // step 8 covering wn..wn+8*NJ = 32 = WN. Consistent: NJ=4 for BN=64, NJ=2 for BN=32.
    extern __shared__ float smp[];
    float* As = smp;                    // [3][128][20] (each float = bf16 pair)
    float* Bs = smp + 3 * 128 * 20;     // [3][BN][20]
#define ASA(s,r,c) As[(((s) * 128) + (r)) * 20 + (c)]
#define BSA(s,r,c) Bs[((s) * BN + (r)) * 20 + (c)]

    const int tid  = threadIdx.x;
    const int wid  = tid >> 5, lane = tid & 31;
    const int g    = lane >> 2, tg = lane & 3;
    const int wm   = (wid & 3) << 5;      // 0,32,64,96
    const int wn   = (wid >> 2) * WN;     // 0 or WN
    const int m0   = blockIdx.x * 128;
    const int n0   = blockIdx.y * BN;
    const int z    = blockIdx.z;

    A    += (size_t)z * zA;
    WT   += (size_t)z * zB;
    bias += z * zbias;

    // cp.async load mapping
    const int ar  = tid >> 1;                 // A row 0..127
    const int aw  = (tid & 1) << 3;           // A word offset 0 or 8
    const int br  = tid >> 2;                 // B row
    const int bw  = (tid & 3) << 2;           // B word offset 0,4,8,12
    const uint32_t aval = ((m0 + ar) < Mrows) ? 16u : 0u;
    const bool bldr = (BN == 64) || (tid < 128);
    const bf16* agp = A  + (size_t)(m0 + ar) * lda + (aw << 1);
    const bf16* bgp = WT + (size_t)(n0 + br) * ldb + (bw << 1);

    // ldmatrix lane addressing
    const int a_lm_row = wm + (lane & 15);          // + mi*16
    const int a_lm_col = (lane >> 4) << 2;          // + ks
    const int b_lm_row = wn + ((lane >> 4) << 3) + (lane & 7);
    const int b_lm_col = ((lane >> 3) & 1) << 2;    // + ks

    const int niter = Klen >> 5;   // K=32 per stage

    auto issue = [&](int kb, int s) {
        uint32_t sa = (uint32_t)__cvta_generic_to_shared(&ASA(s, ar, aw));
        CP_ASYNC16(sa,      agp + (kb << 5),     aval);
        CP_ASYNC16(sa + 16, agp + (kb << 5) + 8, aval);
        if (bldr) {
            uint32_t sb = (uint32_t)__cvta_generic_to_shared(&BSA(s, br, bw));
            CP_ASYNC16(sb, bgp + (kb << 5), 16u);
        }
    };

    float acc[2][NJ][4];
    #pragma unroll
    for (int i = 0; i < 2; i++)
        #pragma unroll
        for (int j = 0; j < NJ; j++)
            #pragma unroll
            for (int v = 0; v < 4; v++) acc[i][j][v] = 0.f;

    issue(0, 0); CP_COMMIT();
    issue(1, 1); CP_COMMIT();

    for (int it = 0; it < niter; it++) {
        const int s = it % 3;
        CP_WAIT1();
        __syncthreads();
        if (it + 2 < niter) issue(it + 2, (it + 2) % 3);
        CP_COMMIT();

        // preload all fragments for this k-block (2 k16 steps) via ldmatrix
        uint32_t af[2][2][4];           // [ks][mi][4]
        uint32_t bfr[2][NJ][2];         // [ks][nj][2]
        #pragma unroll
        for (int kq = 0; kq < 2; kq++) {
            const int ks = kq << 3;
            #pragma unroll
            for (int mi = 0; mi < 2; mi++)
                ldsm_x4(af[kq][mi][0], af[kq][mi][1], af[kq][mi][2], af[kq][mi][3],
                        &ASA(s, a_lm_row + (mi << 4), ks + a_lm_col));
            #pragma unroll
            for (int nq = 0; nq < NJ / 2; nq++) {
                uint32_t r0, r1, r2, r3;
                ldsm_x4(r0, r1, r2, r3,
                        &BSA(s, b_lm_row + (nq << 4), ks + b_lm_col));
                bfr[kq][nq * 2 + 0][0] = r0; bfr[kq][nq * 2 + 0][1] = r1;
                bfr[kq][nq * 2 + 1][0] = r2; bfr[kq][nq * 2 + 1][1] = r3;
            }
        }
        #pragma unroll
        for (int kq = 0; kq < 2; kq++)
            #pragma unroll
            for (int mi = 0; mi < 2; mi++)
                #pragma unroll
                for (int nj = 0; nj < NJ; nj++)
                    MMA_BF16(acc[mi][nj], af[kq][mi], bfr[kq][nj]);
    }

    // epilogue
    #pragma unroll
    for (int nj = 0; nj < NJ; nj++) {
        const int cloc = n0 + wn + (nj << 3) + (tg << 1);
        const int col  = cloc + z * zC;
        const float2 bv = *(const float2*)&bias[cloc];
        #pragma unroll
        for (int mi = 0; mi < 2; mi++) {
            const int row0 = m0 + wm + (mi << 4) + g;
            const int row1 = row0 + 8;
            float2 v0 = make_float2(acc[mi][nj][0], acc[mi][nj][1]);
            float2 v1 = make_float2(acc[mi][nj][2], acc[mi][nj][3]);
            if (EPI == 0) {
                v0.x += bv.x; v0.y += bv.y; v1.x += bv.x; v1.y += bv.y;
            } else if (EPI == 1) {
                v0.x = fmaxf(v0.x + bv.x, 0.f); v0.y = fmaxf(v0.y + bv.y, 0.f);
                v1.x = fmaxf(v1.x + bv.x, 0.f); v1.y = fmaxf(v1.y + bv.y, 0.f);
            }
            if (row0 < Mrows) {
                if (EPI == 2) {
                    const float ws = wsum[(size_t)row0 * 8 + z];
                    v0.x += ws * bv.x; v0.y += ws * bv.y;
                }
                if (OBF) {
                    bf162 p = __floats2bfloat162_rn(v0.x, v0.y);
                    *(bf162*)((bf16*)Cg + (size_t)row0 * ldc + col) = p;
                } else {
                    *(float2*)((float*)Cg + (size_t)row0 * ldc + col) = v0;
                }
            }
            if (row1 < Mrows) {
                if (EPI == 2) {
                    const float ws = wsum[(size_t)row1 * 8 + z];
                    v1.x += ws * bv.x; v1.y += ws * bv.y;
                }
                if (OBF) {
                    bf162 p = __floats2bfloat162_rn(v1.x, v1.y);
                    *(bf162*)((bf16*)Cg + (size_t)row1 * ldc + col) = p;
                } else {
                    *(float2*)((float*)Cg + (size_t)row1 * ldc + col) = v1;
                }
            }
        }
    }
#undef ASA
#undef BSA
}

// ---------------- deformable sampling + aggregation (bf16 output) ----------------
__global__ __launch_bounds__(256) void sample_agg_kernel(
    const float* __restrict__ value, const float* __restrict__ ref_points)
{
    const int r    = blockIdx.x;
    const int b    = r / NQ_;
    const int m    = threadIdx.x >> 5;
    const int lane = threadIdx.x & 31;

    const float rx = ref_points[r * 2 + 0];
    const float ry = ref_points[r * 2 + 1];

    float araw = (lane < 16) ? g_qout[(size_t)r * 384 + 256 + m * 16 + lane] : -1e30f;
    float amax = araw;
    #pragma unroll
    for (int o = 8; o; o >>= 1) amax = fmaxf(amax, __shfl_xor_sync(FULLMASK, amax, o, 16));
    float e = (lane < 16) ? __expf(araw - amax) : 0.f;
    float es = e;
    #pragma unroll
    for (int o = 8; o; o >>= 1) es += __shfl_xor_sync(FULLMASK, es, o, 16);
    const float anorm = e / es;

    const float offv = g_qout[(size_t)r * 384 + m * 32 + lane];

    float a0[4] = {0.f, 0.f, 0.f, 0.f};
    float a1[4] = {0.f, 0.f, 0.f, 0.f};
    float wsum = 0.f;

    const int Hs[4]  = {92, 46, 23, 12};
    const int Wls[4] = {160, 80, 40, 20};
    const int St[4]  = {0, 14720, 18400, 19320};
    const float* vb = value + (size_t)b * S_ * C_;

#define ACCUM(ptr, wgt) do {                                          \
        const float4* _p4 = (const float4*)(ptr);                     \
        float4 _v0 = _p4[lane];                                       \
        float4 _v1 = _p4[32 + lane];                                  \
        a0[0] = fmaf(wgt, _v0.x, a0[0]);                              \
        a0[1] = fmaf(wgt, _v0.y, a0[1]);                              \
        a0[2] = fmaf(wgt, _v0.z, a0[2]);                              \
        a0[3] = fmaf(wgt, _v0.w, a0[3]);                              \
        a1[0] = fmaf(wgt, _v1.x, a1[0]);                              \
        a1[1] = fmaf(wgt, _v1.y, a1[1]);                              \
        a1[2] = fmaf(wgt, _v1.z, a1[2]);                              \
        a1[3] = fmaf(wgt, _v1.w, a1[3]);                              \
    } while (0)

    #pragma unroll
    for (int l = 0; l < 4; l++) {
        const int Hl = Hs[l], Wl = Wls[l];
        const float invW = 1.f / (float)Wl, invH = 1.f / (float)Hl;
        const float* lb = vb + (size_t)St[l] * C_;
        #pragma unroll
        for (int p = 0; p < 4; p++) {
            const int pt = l * 4 + p;
            const float a  = __shfl_sync(FULLMASK, anorm, pt);
            const float ox = __shfl_sync(FULLMASK, offv, 2 * pt);
            const float oy = __shfl_sync(FULLMASK, offv, 2 * pt + 1);
            const float x = (rx + ox * invW) * (float)Wl - 0.5f;
            const float y = (ry + oy * invH) * (float)Hl - 0.5f;
            const float xf = floorf(x), yf = floorf(y);
            const int   x0 = (int)xf,   y0 = (int)yf;
            const float lx = x - xf,    ly = y - yf;
            const float w00 = a * (1.f - lx) * (1.f - ly);
            const float w01 = a * lx * (1.f - ly);
            const float w10 = a * (1.f - lx) * ly;
            const float w11 = a * lx * ly;
            const bool vx0 = (unsigned)x0       < (unsigned)Wl;
            const bool vx1 = (unsigned)(x0 + 1) < (unsigned)Wl;
            const bool vy0 = (unsigned)y0       < (unsigned)Hl;
            const bool vy1 = (unsigned)(y0 + 1) < (unsigned)Hl;
            if (vy0) {
                const float* rp = lb + (size_t)y0 * Wl * C_;
                if (vx0) { ACCUM(rp + (size_t)x0 * C_,       w00); wsum += w00; }
                if (vx1) { ACCUM(rp + (size_t)(x0 + 1) * C_, w01); wsum += w01; }
            }
            if (vy1) {
                const float* rp = lb + (size_t)(y0 + 1) * Wl * C_;
                if (vx0) { ACCUM(rp + (size_t)x0 * C_,       w10); wsum += w10; }
                if (vx1) { ACCUM(rp + (size_t)(x0 + 1) * C_, w11); wsum += w11; }
            }
        }
    }
#undef ACCUM

    bf16* ag = g_aggh + ((size_t)r * M_ + m) * C_;
    {
        bf162 p0 = __floats2bfloat162_rn(a0[0], a0[1]);
        bf162 p1 = __floats2bfloat162_rn(a0[2], a0[3]);
        uint2 u; u.x = *(uint32_t*)&p0; u.y = *(uint32_t*)&p1;
        *(uint2*)(ag + lane * 4) = u;
        p0 = __floats2bfloat162_rn(a1[0], a1[1]);
        p1 = __floats2bfloat162_rn(a1[2], a1[3]);
        u.x = *(uint32_t*)&p0; u.y = *(uint32_t*)&p1;
        *(uint2*)(ag + 128 + lane * 4) = u;
    }
    if (lane == 0) g_wsum[(size_t)r * M_ + m] = wsum;
}

// ---------------- LayerNorm helpers ----------------
__global__ __launch_bounds__(256) void ln1_kernel(
    const float* __restrict__ query,
    const float* __restrict__ lw, const float* __restrict__ lb)
{
    const int r = blockIdx.x, t = threadIdx.x;
    const size_t idx = (size_t)r * C_ + t;
    float v = query[idx] + g_feat[idx];

    __shared__ float s1[8], s2[8];
    float sum = v, sq = v * v;
    #pragma unroll
    for (int o = 16; o; o >>= 1) {
        sum += __shfl_xor_sync(FULLMASK, sum, o);
        sq  += __shfl_xor_sync(FULLMASK, sq, o);
    }
    const int lane = t & 31, wp = t >> 5;
    if (lane == 0) { s1[wp] = sum; s2[wp] = sq; }
    __syncthreads();
    float tot = 0.f, totq = 0.f;
    #pragma unroll
    for (int i = 0; i < 8; i++) { tot += s1[i]; totq += s2[i]; }
    const float mu  = tot * (1.f / 256.f);
    const float var = totq * (1.f / 256.f) - mu * mu;
    const float rs  = rsqrtf(var + 1e-6f);
    const float o   = (v - mu) * rs * lw[t] + lb[t];
    g_x1[idx]  = o;
    g_x1h[idx] = __float2bfloat16_rn(o);
}

__global__ __launch_bounds__(256) void ln2_cls_kernel(
    const float* __restrict__ lw, const float* __restrict__ lb,
    const float* __restrict__ wcls, const float* __restrict__ bcls,
    float* __restrict__ out)
{
    const int r = blockIdx.x, t = threadIdx.x;
    const size_t idx = (size_t)r * C_ + t;
    float v = g_x1[idx] + g_h2[idx];

    __shared__ float s1[8], s2[8];
    __shared__ float sred[8][10];
    float sum = v, sq = v * v;
    #pragma unroll
    for (int o = 16; o; o >>= 1) {
        sum += __shfl_xor_sync(FULLMASK, sum, o);
        sq  += __shfl_xor_sync(FULLMASK, sq, o);
    }
    const int lane = t & 31, wp = t >> 5;
    if (lane == 0) { s1[wp] = sum; s2[wp] = sq; }
    __syncthreads();
    float tot = 0.f, totq = 0.f;
    #pragma unroll
    for (int i = 0; i < 8; i++) { tot += s1[i]; totq += s2[i]; }
    const float mu  = tot * (1.f / 256.f);
    const float var = totq * (1.f / 256.f) - mu * mu;
    const float rs  = rsqrtf(var + 1e-6f);
    const float x2  = (v - mu) * rs * lw[t] + lb[t];

    float pr[10];
    #pragma unroll
    for (int j = 0; j < 10; j++) pr[j] = x2 * wcls[t * 10 + j];
    #pragma unroll
    for (int o = 16; o; o >>= 1)
        #pragma unroll
        for (int j = 0; j < 10; j++) pr[j] += __shfl_xor_sync(FULLMASK, pr[j], o);
    if (lane == 0)
        #pragma unroll
        for (int j = 0; j < 10; j++) sred[wp][j] = pr[j];
    __syncthreads();
    if (t < 10) {
        float s = bcls[t];
        #pragma unroll
        for (int i = 0; i < 8; i++) s += sred[i][t];
        out[(size_t)r * NC_ + t] = s;
    }
}

// ---------------- launch ----------------
#define SMEM64 ((3*128*20 + 3*64*20) * 4)   // 46080
#define SMEM32 ((3*128*20 + 3*32*20) * 4)   // 38400

extern "C" void kernel_launch(void* const* d_in, const int* in_sizes, int n_in,
                              void* d_out, int out_size)
{
    const float* query  = (const float*)d_in[0];
    const float* value  = (const float*)d_in[1];
    const float* refp   = (const float*)d_in[2];
    const float* w_value= (const float*)d_in[3];
    const float* b_value= (const float*)d_in[4];
    const float* w_off  = (const float*)d_in[5];
    const float* b_off  = (const float*)d_in[6];
    const float* w_attn = (const float*)d_in[7];
    const float* b_attn = (const float*)d_in[8];
    const float* w_out  = (const float*)d_in[9];
    const float* b_out  = (const float*)d_in[10];
    const float* ln1w   = (const float*)d_in[11];
    const float* ln1b   = (const float*)d_in[12];
    const float* w_ffn1 = (const float*)d_in[13];
    const float* b_ffn1 = (const float*)d_in[14];
    const float* w_ffn2 = (const float*)d_in[15];
    const float* b_ffn2 = (const float*)d_in[16];
    const float* ln2w   = (const float*)d_in[17];
    const float* ln2b   = (const float*)d_in[18];
    const float* w_cls  = (const float*)d_in[19];
    const float* b_cls  = (const float*)d_in[20];
    float* out = (float*)d_out;

    float *p_qout, *p_wsum, *p_feat, *p_x1, *p_h2, *p_bq;
    bf16  *p_aggh, *p_featvh, *p_x1h, *p_hh, *p_qbf;
    bf16  *p_wqTh, *p_woutTh, *p_f1Th, *p_f2Th, *p_wvTh;
    cudaGetSymbolAddress((void**)&p_qout,   g_qout);
    cudaGetSymbolAddress((void**)&p_aggh,   g_aggh);
    cudaGetSymbolAddress((void**)&p_wsum,   g_wsum);
    cudaGetSymbolAddress((void**)&p_featvh, g_featvh);
    cudaGetSymbolAddress((void**)&p_feat,   g_feat);
    cudaGetSymbolAddress((void**)&p_x1,     g_x1);
    cudaGetSymbolAddress((void**)&p_x1h,    g_x1h);
    cudaGetSymbolAddress((void**)&p_hh,     g_hh);
    cudaGetSymbolAddress((void**)&p_h2,     g_h2);
    cudaGetSymbolAddress((void**)&p_qbf,    g_qbf);
    cudaGetSymbolAddress((void**)&p_wqTh,   g_wqTh);
    cudaGetSymbolAddress((void**)&p_bq,     g_bq);
    cudaGetSymbolAddress((void**)&p_woutTh, g_woutTh);
    cudaGetSymbolAddress((void**)&p_f1Th,   g_f1Th);
    cudaGetSymbolAddress((void**)&p_f2Th,   g_f2Th);
    cudaGetSymbolAddress((void**)&p_wvTh,   g_wvTh);

    cudaFuncSetAttribute(gemm_bf<64,0,0>, cudaFuncAttributeMaxDynamicSharedMemorySize, SMEM64);
    cudaFuncSetAttribute(gemm_bf<64,1,1>, cudaFuncAttributeMaxDynamicSharedMemorySize, SMEM64);
    cudaFuncSetAttribute(gemm_bf<32,2,1>, cudaFuncAttributeMaxDynamicSharedMemorySize, SMEM32);

    // 0. weight + query bf16 prep
    prep_weights<<<9990, 256>>>(query, w_off, w_attn, b_off, b_attn,
                                w_out, w_ffn1, w_ffn2, w_value);
    // 1. fused query projection: [off | attn] = q @ [w_off | w_attn]
    gemm_bf<64,0,0><<<dim3(MT_, 6), 256, SMEM64>>>(p_qbf, C_, 0, p_wqTh, 256, 0, p_bq, 0,
                                                   nullptr, p_qout, 384, 0, R_, 256);
    // 2. deformable sampling + weighted aggregation (bf16 agg out)
    sample_agg_kernel<<<R_, 256>>>(value, refp);
    // 3. per-head value projection (thin GEMM N=32 per head, z = 8)
    gemm_bf<32,2,1><<<dim3(MT_, 1, M_), 256, SMEM32>>>(p_aggh, 2048, 256, p_wvTh, 256, 8192,
                                                       b_value, 32, p_wsum,
                                                       p_featvh, C_, 32, R_, 256);
    // 4. output projection (fp32 out for LN)
    gemm_bf<64,0,0><<<dim3(MT_, 4), 256, SMEM64>>>(p_featvh, C_, 0, p_woutTh, 256, 0, b_out, 0,
                                                   nullptr, p_feat, C_, 0, R_, 256);
    // 5. residual + LN1 (fp32 + bf16 mirror)
    ln1_kernel<<<R_, 256>>>(query, ln1w, ln1b);
    // 6. FFN
    gemm_bf<64,1,1><<<dim3(MT_, 16), 256, SMEM64>>>(p_x1h, C_, 0, p_f1Th, 256, 0, b_ffn1, 0,
                                                    nullptr, p_hh, FFN_, 0, R_, 256);
    gemm_bf<64,0,0><<<dim3(MT_, 4), 256, SMEM64>>>(p_hh, FFN_, 0, p_f2Th, 1024, 0, b_ffn2, 0,
                                                   nullptr, p_h2, C_, 0, R_, 1024);
    // 7. residual + LN2 + classifier
    ln2_cls_kernel<<<R_, 256>>>(ln2w, ln2b, w_cls, b_cls, out);
}